// round 12
// baseline (speedup 1.0000x reference)
#include <cuda_runtime.h>
#include <cuda_bf16.h>
#include <math.h>
#include <stdint.h>

// ---------------------------------------------------------------------------
// Problem constants
// ---------------------------------------------------------------------------
#define NMAX   16000
#define EMAX   256000
#define ETMAX  (EMAX + NMAX)
#define HEADS  4
#define MAXHC  512
#define NGRAPH 64
#define MAXK2  480

#define WOFF_L0L 0
#define WOFF_L0R 245760
#define WOFF_L1L 491520
#define WOFF_L1R 557056
#define WOFF_L2L 622592
#define WOFF_L2R 638976
#define WOFF_AW1 655360
#define WTOTAL   663552

// GEMM smem: 3 stages x 24576 bytes
#define STAGE_BYTES 24576
#define GEMM_SMEM   (3 * STAGE_BYTES)

// ---------------------------------------------------------------------------
// Static device scratch
// ---------------------------------------------------------------------------
__device__ float    g_xl   [NMAX * MAXHC];
__device__ float    g_xr   [NMAX * MAXHC];
__device__ float    g_act0 [NMAX * MAXHC];
__device__ float    g_act1 [NMAX * MAXHC];
__device__ float    g_stats[2 * MAXHC];
__device__ float    g_colA [MAXHC];
__device__ float    g_colS [MAXHC];
__device__ float    g_hidden[NMAX * 128];
__device__ float    g_gate [NMAX];
__device__ uint32_t g_xph  [NMAX * MAXK2];
__device__ uint32_t g_xpl  [NMAX * MAXK2];
__device__ uint32_t g_wph  [WTOTAL];
__device__ uint32_t g_wpl  [WTOTAL];
__device__ int      g_deg  [NMAX];
__device__ int      g_ptr  [NMAX + 1];
__device__ int      g_pos  [NMAX];
__device__ int      g_csrc [ETMAX];

// ---------------------------------------------------------------------------
// Helpers
// ---------------------------------------------------------------------------
__device__ __forceinline__ void packsplit(float x0, float x1,
                                          uint32_t& hi, uint32_t& lo) {
    __nv_bfloat16 h0 = __float2bfloat16_rn(x0);
    __nv_bfloat16 h1 = __float2bfloat16_rn(x1);
    float l0f = x0 - __bfloat162float(h0);
    float l1f = x1 - __bfloat162float(h1);
    __nv_bfloat16 l0 = __float2bfloat16_rn(l0f);
    __nv_bfloat16 l1 = __float2bfloat16_rn(l1f);
    __nv_bfloat162 hp = __halves2bfloat162(h0, h1);
    __nv_bfloat162 lp = __halves2bfloat162(l0, l1);
    hi = *reinterpret_cast<uint32_t*>(&hp);
    lo = *reinterpret_cast<uint32_t*>(&lp);
}

__global__ void fill_f_kernel(float* __restrict__ p, float v, int n) {
    int i = blockIdx.x * blockDim.x + threadIdx.x;
    if (i < n) p[i] = v;
}
__global__ void fill_i_kernel(int* __restrict__ p, int v, int n) {
    int i = blockIdx.x * blockDim.x + threadIdx.x;
    if (i < n) p[i] = v;
}

__global__ void split_pack_A_kernel(const float2* __restrict__ in,
                                    uint32_t* __restrict__ hi, uint32_t* __restrict__ lo,
                                    int n2) {
    int i = blockIdx.x * blockDim.x + threadIdx.x;
    if (i >= n2) return;
    float2 v = in[i];
    uint32_t h, l;
    packsplit(v.x, v.y, h, l);
    hi[i] = h; lo[i] = l;
}

// pack fp32 [K, HC] -> hi/lo uint32 in N-MAJOR layout [HC, K/2]
__global__ void split_pack_B_kernel(const float* __restrict__ W,
                                    uint32_t* __restrict__ hi, uint32_t* __restrict__ lo,
                                    int K2, int HC) {
    int i = blockIdx.x * blockDim.x + threadIdx.x;
    if (i >= K2 * HC) return;
    int n = i / K2, kp = i - n * K2;
    float x0 = W[(size_t)(2 * kp) * HC + n];
    float x1 = W[(size_t)(2 * kp + 1) * HC + n];
    uint32_t h, l;
    packsplit(x0, x1, h, l);
    hi[(size_t)n * K2 + kp] = h;
    lo[(size_t)n * K2 + kp] = l;
}

// ---------------------------------------------------------------------------
// CSR build over dst; stores gathered src per CSR slot.
// ---------------------------------------------------------------------------
__global__ void csr_count_kernel(const int* __restrict__ dst, int* __restrict__ deg,
                                 int E, int Nn) {
    int e = blockIdx.x * blockDim.x + threadIdx.x;
    int Et = E + Nn;
    if (e >= Et) return;
    int d = (e < E) ? dst[e] : (e - E);
    atomicAdd(&deg[d], 1);
}

__global__ void csr_scan_kernel(const int* __restrict__ deg, int* __restrict__ ptr,
                                int* __restrict__ pos, int n) {
    __shared__ int ss[1024];
    int t = threadIdx.x;
    int base = t * 16;
    int loc[16];
    int s = 0;
    #pragma unroll
    for (int i = 0; i < 16; i++) {
        int v = (base + i < n) ? deg[base + i] : 0;
        loc[i] = v; s += v;
    }
    ss[t] = s;
    __syncthreads();
    for (int off = 1; off < 1024; off <<= 1) {
        int v = (t >= off) ? ss[t - off] : 0;
        __syncthreads();
        ss[t] += v;
        __syncthreads();
    }
    int run = (t > 0) ? ss[t - 1] : 0;
    #pragma unroll
    for (int i = 0; i < 16; i++) {
        if (base + i < n) {
            ptr[base + i] = run;
            pos[base + i] = run;
            run += loc[i];
        }
    }
    if (t == 1023) ptr[n] = ss[1023];
}

__global__ void csr_scatter_kernel(const int* __restrict__ src, const int* __restrict__ dst,
                                   int* __restrict__ pos, int* __restrict__ csrc,
                                   int E, int Nn) {
    int e = blockIdx.x * blockDim.x + threadIdx.x;
    int Et = E + Nn;
    if (e >= Et) return;
    int d, s;
    if (e < E) { d = dst[e]; s = src[e]; } else { d = s = e - E; }
    int slot = atomicAdd(&pos[d], 1);
    csrc[slot] = s;
}

// ---------------------------------------------------------------------------
// bf16 3-term tensor-core GEMM: 3-stage cp.async ring + ldmatrix fragments.
// A: hi/lo uint32 [M, K2]; B: hi/lo uint32 N-MAJOR [HC, K2].
// Block 128x128x(8 k-pairs), 8 warps (2x4), warp tile 64x32, mma m16n8k16.
// Per-stage layout (byte offsets): AH +0, AL +6144, BH +12288, BL +18432.
// Row pitch 12 words (8 data + 4 pad) -> conflict-free ldmatrix.
// ---------------------------------------------------------------------------
__device__ __forceinline__ void mma_bf16(float* d, const uint32_t* a, const uint32_t* b) {
    asm volatile(
        "mma.sync.aligned.m16n8k16.row.col.f32.bf16.bf16.f32 "
        "{%0,%1,%2,%3}, {%4,%5,%6,%7}, {%8,%9}, {%0,%1,%2,%3};\n"
        : "+f"(d[0]), "+f"(d[1]), "+f"(d[2]), "+f"(d[3])
        : "r"(a[0]), "r"(a[1]), "r"(a[2]), "r"(a[3]), "r"(b[0]), "r"(b[1]));
}

#define LDSM4(r, a) asm volatile( \
    "ldmatrix.sync.aligned.m8n8.x4.shared.b16 {%0,%1,%2,%3}, [%4];" \
    : "=r"((r)[0]), "=r"((r)[1]), "=r"((r)[2]), "=r"((r)[3]) : "r"(a))
#define LDSM2(r0, r1, a) asm volatile( \
    "ldmatrix.sync.aligned.m8n8.x2.shared.b16 {%0,%1}, [%2];" \
    : "=r"(r0), "=r"(r1) : "r"(a))
#define CPA16(s, g) asm volatile( \
    "cp.async.cg.shared.global [%0], [%1], 16;" :: "r"(s), "l"(g))
#define CPCOMMIT() asm volatile("cp.async.commit_group;")
#define CPWAIT0()  asm volatile("cp.async.wait_group 0;")
#define CPWAIT1()  asm volatile("cp.async.wait_group 1;")

__global__ void __launch_bounds__(256)
bf16gemm_pre(const uint32_t* __restrict__ XH, const uint32_t* __restrict__ XL,
             const uint32_t* __restrict__ WH0, const uint32_t* __restrict__ WL0,
             const uint32_t* __restrict__ WH1, const uint32_t* __restrict__ WL1,
             float* __restrict__ out0, float* __restrict__ out1,
             const float* __restrict__ bias, int relu,
             int M, int K2, int HC) {
    extern __shared__ uint32_t S[];
    uint32_t sbase = (uint32_t)__cvta_generic_to_shared(S);

    const int t  = threadIdx.x;
    const int bm = blockIdx.y * 128;
    int bn = blockIdx.x * 128;

    const uint32_t* WH = WH0;
    const uint32_t* WL = WL0;
    float* out = out0;
    int col0 = bn;
    if (WH1 != nullptr && bn >= HC) { WH = WH1; WL = WL1; out = out1; col0 = bn - HC; }

    // cp.async loaders: thread -> (row = t>>1, 16B seg = t&1)
    const int lrow = t >> 1;
    const int lseg = t & 1;
    const uint32_t* ApH = XH + (size_t)(bm + lrow) * K2 + lseg * 4;
    const uint32_t* ApL = XL + (size_t)(bm + lrow) * K2 + lseg * 4;
    const uint32_t* BpH = WH + (size_t)(col0 + lrow) * K2 + lseg * 4;
    const uint32_t* BpL = WL + (size_t)(col0 + lrow) * K2 + lseg * 4;
    const uint32_t sst = sbase + (lrow * 12 + lseg * 4) * 4;   // AH intra-stage addr

    // warp/lane geometry
    const int wA   = t >> 5;
    const int lane = t & 31;
    const int m0w = (wA >> 2) * 64;
    const int n0w = (wA & 3) * 32;
    const int tq   = lane & 3;
    const int trow = lane >> 2;

    // ldmatrix intra-stage fragment addresses (bytes)
    const uint32_t afo = sbase +
        ((m0w + (lane & 7) + ((lane >> 3) & 1) * 8) * 12 + ((lane >> 4) & 1) * 4) * 4;
    const uint32_t bfo = sbase + 12288 +
        ((n0w + (lane & 7)) * 12 + ((lane >> 3) & 1) * 4) * 4;

    float acc[4][4][4];
    #pragma unroll
    for (int i = 0; i < 4; i++)
        #pragma unroll
        for (int j = 0; j < 4; j++)
            #pragma unroll
            for (int r = 0; r < 4; r++) acc[i][j][r] = 0.f;

    const int nt = K2 >> 3;

    // prologue: tiles 0 and 1 into stages 0 and 1
    {
        CPA16(sst,          ApH);
        CPA16(sst + 6144,   ApL);
        CPA16(sst + 12288,  BpH);
        CPA16(sst + 18432,  BpL);
        CPCOMMIT();
        if (1 < nt) {
            uint32_t o = STAGE_BYTES;
            CPA16(sst + o,          ApH + 8);
            CPA16(sst + o + 6144,   ApL + 8);
            CPA16(sst + o + 12288,  BpH + 8);
            CPA16(sst + o + 18432,  BpL + 8);
            CPCOMMIT();
        }
    }

    int stage = 0;           // stage of tile `it`
    int wstage = (nt >= 2) ? 2 : 1;   // next stage to write
    for (int it = 0; it < nt; it++) {
        if (it + 1 < nt) { CPWAIT1(); } else { CPWAIT0(); }
        __syncthreads();
        if (it + 2 < nt) {
            int p0 = (it + 2) << 3;
            uint32_t o = (uint32_t)wstage * STAGE_BYTES;
            CPA16(sst + o,          ApH + p0);
            CPA16(sst + o + 6144,   ApL + p0);
            CPA16(sst + o + 12288,  BpH + p0);
            CPA16(sst + o + 18432,  BpL + p0);
            CPCOMMIT();
            wstage = (wstage == 2) ? 0 : wstage + 1;
        }

        uint32_t ob = (uint32_t)stage * STAGE_BYTES;
        uint32_t aH[4][4], aL[4][4];
        #pragma unroll
        for (int i = 0; i < 4; i++) {
            LDSM4(aH[i], afo + ob + i * 768);
            LDSM4(aL[i], afo + ob + i * 768 + 6144);
        }
        #pragma unroll
        for (int j = 0; j < 4; j++) {
            uint32_t bH[2], bL[2];
            LDSM2(bH[0], bH[1], bfo + ob + j * 384);
            LDSM2(bL[0], bL[1], bfo + ob + j * 384 + 6144);
            #pragma unroll
            for (int i = 0; i < 4; i++) {
                mma_bf16(acc[i][j], aH[i], bH);
                mma_bf16(acc[i][j], aH[i], bL);
                mma_bf16(acc[i][j], aL[i], bH);
            }
        }
        stage = (stage == 2) ? 0 : stage + 1;
    }

    // epilogue
    #pragma unroll
    for (int i = 0; i < 4; i++) {
        int gr0 = bm + m0w + i * 16 + trow;
        #pragma unroll
        for (int j = 0; j < 4; j++) {
            int gc = col0 + n0w + j * 8 + tq * 2;
            float2 v0 = make_float2(acc[i][j][0], acc[i][j][1]);
            float2 v1 = make_float2(acc[i][j][2], acc[i][j][3]);
            if (bias) {
                float b0 = bias[gc], b1 = bias[gc + 1];
                v0.x += b0; v0.y += b1;
                v1.x += b0; v1.y += b1;
            }
            if (relu) {
                v0.x = fmaxf(v0.x, 0.f); v0.y = fmaxf(v0.y, 0.f);
                v1.x = fmaxf(v1.x, 0.f); v1.y = fmaxf(v1.y, 0.f);
            }
            *(float2*)&out[(size_t)gr0 * HC + gc]       = v0;
            *(float2*)&out[(size_t)(gr0 + 8) * HC + gc] = v1;
        }
    }
}

// ---------------------------------------------------------------------------
// Fused GATv2 edge phase (unconditional online-softmax update).
// ---------------------------------------------------------------------------
template <int NV4, int CSH>
__global__ void gat_edge_fused(const float4* __restrict__ xl4,
                               const float4* __restrict__ xr4,
                               const float4* __restrict__ att4,
                               const int* __restrict__ ptr,
                               const int* __restrict__ csrc,
                               float4* __restrict__ out4, int Nn) {
    int n    = (blockIdx.x * blockDim.x + threadIdx.x) >> 5;
    int lane = threadIdx.x & 31;
    if (n >= Nn) return;
    const int HC4 = NV4 * 32;

    float4 xr[NV4], at[NV4];
    #pragma unroll
    for (int r = 0; r < NV4; r++) {
        xr[r] = xr4[(size_t)n * HC4 + r * 32 + lane];
        at[r] = att4[r * 32 + lane];
    }

    float m[NV4], z[NV4];
    float4 acc[NV4];
    #pragma unroll
    for (int r = 0; r < NV4; r++) {
        m[r] = -1e30f; z[r] = 0.f;
        acc[r] = make_float4(0.f, 0.f, 0.f, 0.f);
    }

    int beg = ptr[n], end = ptr[n + 1];
    if (beg >= end) return;

    float4 xv[NV4];
    {
        int s = csrc[beg];
        #pragma unroll
        for (int r = 0; r < NV4; r++)
            xv[r] = xl4[(size_t)s * HC4 + r * 32 + lane];
    }

    for (int i = beg; i < end; i++) {
        float4 xn[NV4];
        bool more = (i + 1 < end);
        if (more) {
            int s2 = csrc[i + 1];
            #pragma unroll
            for (int r = 0; r < NV4; r++)
                xn[r] = xl4[(size_t)s2 * HC4 + r * 32 + lane];
        }

        float p[NV4];
        #pragma unroll
        for (int r = 0; r < NV4; r++) {
            float v, s = 0.f;
            v = xv[r].x + xr[r].x; v = (v > 0.f) ? v : 0.2f * v; s += at[r].x * v;
            v = xv[r].y + xr[r].y; v = (v > 0.f) ? v : 0.2f * v; s += at[r].y * v;
            v = xv[r].z + xr[r].z; v = (v > 0.f) ? v : 0.2f * v; s += at[r].z * v;
            v = xv[r].w + xr[r].w; v = (v > 0.f) ? v : 0.2f * v; s += at[r].w * v;
            p[r] = s;
        }
        #pragma unroll
        for (int r = 0; r < NV4; r++) {
            #pragma unroll
            for (int off = (1 << CSH) >> 1; off > 0; off >>= 1)
                p[r] += __shfl_xor_sync(0xffffffffu, p[r], off);
        }
        #pragma unroll
        for (int r = 0; r < NV4; r++) {
            float mn = fmaxf(m[r], p[r]);
            float sc = expf(m[r] - mn);
            float pe = expf(p[r] - mn);
            z[r] = z[r] * sc + pe;
            m[r] = mn;
            acc[r].x = acc[r].x * sc + pe * xv[r].x;
            acc[r].y = acc[r].y * sc + pe * xv[r].y;
            acc[r].z = acc[r].z * sc + pe * xv[r].z;
            acc[r].w = acc[r].w * sc + pe * xv[r].w;
        }
        if (more) {
            #pragma unroll
            for (int r = 0; r < NV4; r++) xv[r] = xn[r];
        }
    }

    #pragma unroll
    for (int r = 0; r < NV4; r++) {
        float inv = 1.f / (z[r] + 1e-16f);
        float4 o;
        o.x = acc[r].x * inv; o.y = acc[r].y * inv;
        o.z = acc[r].z * inv; o.w = acc[r].w * inv;
        out4[(size_t)n * HC4 + r * 32 + lane] = o;
    }
}

// ---------------------------------------------------------------------------
// GraphNorm
// ---------------------------------------------------------------------------
__global__ void colstats_kernel(const float4* __restrict__ x4, float* __restrict__ stats,
                                int Nn, int Cn4, int lg) {
    int r0   = blockIdx.x * 64;
    int rend = min(r0 + 64, Nn);
    int tx  = threadIdx.x & (Cn4 - 1);
    int ty  = threadIdx.x >> lg;
    int nty = 256 >> lg;
    float4 s = make_float4(0.f, 0.f, 0.f, 0.f);
    float4 q = make_float4(0.f, 0.f, 0.f, 0.f);
    for (int r = r0 + ty; r < rend; r += nty) {
        float4 v = x4[(size_t)r * Cn4 + tx];
        s.x += v.x; s.y += v.y; s.z += v.z; s.w += v.w;
        q.x += v.x * v.x; q.y += v.y * v.y; q.z += v.z * v.z; q.w += v.w * v.w;
    }
    int Cn = Cn4 * 4;
    int c = tx * 4;
    atomicAdd(&stats[c + 0], s.x); atomicAdd(&stats[c + 1], s.y);
    atomicAdd(&stats[c + 2], s.z); atomicAdd(&stats[c + 3], s.w);
    atomicAdd(&stats[Cn + c + 0], q.x); atomicAdd(&stats[Cn + c + 1], q.y);
    atomicAdd(&stats[Cn + c + 2], q.z); atomicAdd(&stats[Cn + c + 3], q.w);
}

__global__ void colscale_kernel(const float* __restrict__ stats,
                                const float* __restrict__ bias,
                                const float* __restrict__ gw, const float* __restrict__ gb,
                                const float* __restrict__ gm,
                                float* __restrict__ colA, float* __restrict__ colS,
                                int Nn, int Cn) {
    int c = blockIdx.x * blockDim.x + threadIdx.x;
    if (c >= Cn) return;
    float invN = 1.0f / (float)Nn;
    float ma = stats[c] * invN;
    float q  = stats[Cn + c] * invN;
    float b  = bias[c];
    float mx = ma + b;
    float tt = b - gm[c] * mx;
    float var = q + 2.f * tt * ma + tt * tt;
    var = fmaxf(var, 0.f);
    float A = gw[c] * rsqrtf(var + 1e-5f);
    colA[c] = A;
    colS[c] = A * tt + gb[c];
}

__global__ void norm_relu_split_kernel(float4* __restrict__ x4,
                                       const float4* __restrict__ colA4,
                                       const float4* __restrict__ colS4,
                                       uint32_t* __restrict__ xph,
                                       uint32_t* __restrict__ xpl,
                                       int total4, int Cn4, int wb) {
    int i = blockIdx.x * blockDim.x + threadIdx.x;
    if (i >= total4) return;
    int c = i % Cn4;
    float4 v = x4[i];
    float4 A = colA4[c];
    float4 S = colS4[c];
    v.x = fmaxf(A.x * v.x + S.x, 0.f);
    v.y = fmaxf(A.y * v.y + S.y, 0.f);
    v.z = fmaxf(A.z * v.z + S.z, 0.f);
    v.w = fmaxf(A.w * v.w + S.w, 0.f);
    if (wb) x4[i] = v;
    uint32_t h0, l0, h1, l1;
    packsplit(v.x, v.y, h0, l0);
    packsplit(v.z, v.w, h1, l1);
    xph[2 * i]     = h0; xph[2 * i + 1] = h1;
    xpl[2 * i]     = l0; xpl[2 * i + 1] = l1;
}

// ---------------------------------------------------------------------------
// Pooling
// ---------------------------------------------------------------------------
__global__ void gate_kernel(const float4* __restrict__ hidden4, const float4* __restrict__ aW24,
                            const float* __restrict__ ab2, float* __restrict__ gate, int Nn) {
    int gw   = (blockIdx.x * blockDim.x + threadIdx.x) >> 5;
    int lane = threadIdx.x & 31;
    if (gw >= Nn) return;
    float4 h = hidden4[(size_t)gw * 32 + lane];
    float4 w = aW24[lane];
    float acc = h.x * w.x + h.y * w.y + h.z * w.z + h.w * w.w;
    #pragma unroll
    for (int o = 16; o > 0; o >>= 1) acc += __shfl_down_sync(0xffffffffu, acc, o);
    if (lane == 0) gate[gw] = acc + ab2[0];
}

__device__ __forceinline__ int lower_bound_dev(const int* __restrict__ a, int n, int v) {
    int lo = 0, hi = n;
    while (lo < hi) {
        int mid = (lo + hi) >> 1;
        if (a[mid] < v) lo = mid + 1; else hi = mid;
    }
    return lo;
}

__global__ void pool_kernel(const float* __restrict__ x, const float* __restrict__ gate,
                            const int* __restrict__ batch, float* __restrict__ out, int Nn) {
    __shared__ float red[128];
    __shared__ float wbuf[128];
    int b = blockIdx.x;
    int t = threadIdx.x;
    int beg = lower_bound_dev(batch, Nn, b);
    int end = lower_bound_dev(batch, Nn, b + 1);

    float mx = -1e30f;
    for (int n = beg + t; n < end; n += 128) mx = fmaxf(mx, gate[n]);
    red[t] = mx; __syncthreads();
    for (int o = 64; o > 0; o >>= 1) {
        if (t < o) red[t] = fmaxf(red[t], red[t + o]);
        __syncthreads();
    }
    float m = red[0];
    if (m < -1e29f) m = 0.f;
    __syncthreads();

    float zs = 0.f;
    for (int n = beg + t; n < end; n += 128) zs += expf(gate[n] - m);
    red[t] = zs; __syncthreads();
    for (int o = 64; o > 0; o >>= 1) {
        if (t < o) red[t] += red[t + o];
        __syncthreads();
    }
    float inv = 1.f / (red[0] + 1e-16f);
    __syncthreads();

    float acc = 0.f;
    for (int base = beg; base < end; base += 128) {
        int n = base + t;
        wbuf[t] = (n < end) ? expf(gate[n] - m) * inv : 0.f;
        __syncthreads();
        int cnt = min(128, end - base);
        for (int k = 0; k < cnt; k++)
            acc += wbuf[k] * x[(size_t)(base + k) * 128 + t];
        __syncthreads();
    }
    out[b * 128 + t] = acc;
}

// ---------------------------------------------------------------------------
// Host orchestration
// ---------------------------------------------------------------------------
extern "C" void kernel_launch(void* const* d_in, const int* in_sizes, int n_in,
                              void* d_out, int out_size) {
    const float* x0    = (const float*)d_in[0];
    const int*   ei    = (const int*)d_in[1];
    const int*   batch = (const int*)d_in[2];

    int N = in_sizes[0] / 960;
    int E = in_sizes[1] / 2;
    const int* src = ei;
    const int* dst = ei + E;
    int Et = E + N;

    // Unconditional (no static guard — identical work every call; idempotent,
    // immediate host-side call, safe under graph capture).
    cudaFuncSetAttribute(bf16gemm_pre,
                         cudaFuncAttributeMaxDynamicSharedMemorySize, GEMM_SMEM);

    float *p_xl, *p_xr, *p_a0, *p_a1, *p_stats, *p_colA, *p_colS, *p_hidden, *p_gate;
    uint32_t *p_xph, *p_xpl, *p_wph, *p_wpl;
    int *p_deg, *p_ptr, *p_pos, *p_csrc;
    cudaGetSymbolAddress((void**)&p_xl,    g_xl);
    cudaGetSymbolAddress((void**)&p_xr,    g_xr);
    cudaGetSymbolAddress((void**)&p_a0,    g_act0);
    cudaGetSymbolAddress((void**)&p_a1,    g_act1);
    cudaGetSymbolAddress((void**)&p_stats, g_stats);
    cudaGetSymbolAddress((void**)&p_colA,  g_colA);
    cudaGetSymbolAddress((void**)&p_colS,  g_colS);
    cudaGetSymbolAddress((void**)&p_hidden,g_hidden);
    cudaGetSymbolAddress((void**)&p_gate,  g_gate);
    cudaGetSymbolAddress((void**)&p_xph,   g_xph);
    cudaGetSymbolAddress((void**)&p_xpl,   g_xpl);
    cudaGetSymbolAddress((void**)&p_wph,   g_wph);
    cudaGetSymbolAddress((void**)&p_wpl,   g_wpl);
    cudaGetSymbolAddress((void**)&p_deg,   g_deg);
    cudaGetSymbolAddress((void**)&p_ptr,   g_ptr);
    cudaGetSymbolAddress((void**)&p_pos,   g_pos);
    cudaGetSymbolAddress((void**)&p_csrc,  g_csrc);

    const int woffL[3] = {WOFF_L0L, WOFF_L1L, WOFF_L2L};
    const int woffR[3] = {WOFF_L0R, WOFF_L1R, WOFF_L2R};
    const int din[3] = {960, 512, 256};
    const int Cc[3]  = {128, 64, 32};

    // ---- Launches 1-3: layer-0 operand packs (so launch 4 = GEMM, profiled) ----
    {
        int K2 = 480, HC = 512, nel = K2 * HC;
        split_pack_B_kernel<<<(nel + 255) / 256, 256>>>(
            (const float*)d_in[3], p_wph + WOFF_L0L, p_wpl + WOFF_L0L, K2, HC);
        split_pack_B_kernel<<<(nel + 255) / 256, 256>>>(
            (const float*)d_in[4], p_wph + WOFF_L0R, p_wpl + WOFF_L0R, K2, HC);
    }
    split_pack_A_kernel<<<(N * 480 + 255) / 256, 256>>>(
        (const float2*)x0, p_xph, p_xpl, N * 480);

    // ---- Launch 4: layer-0 dual GEMM (ncu-profiled) ----
    {
        dim3 gblk(2 * 512 / 128, N / 128);
        bf16gemm_pre<<<gblk, 256, GEMM_SMEM>>>(p_xph, p_xpl,
                                    p_wph + WOFF_L0L, p_wpl + WOFF_L0L,
                                    p_wph + WOFF_L0R, p_wpl + WOFF_L0R,
                                    p_xl, p_xr, nullptr, 0, N, 480, 512);
    }

    // ---- CSR build ----
    fill_i_kernel<<<(N + 255) / 256, 256>>>(p_deg, 0, N);
    csr_count_kernel<<<(Et + 255) / 256, 256>>>(dst, p_deg, E, N);
    csr_scan_kernel<<<1, 1024>>>(p_deg, p_ptr, p_pos, N);
    csr_scatter_kernel<<<(Et + 255) / 256, 256>>>(src, dst, p_pos, p_csrc, E, N);

    // ---- Remaining weight packs ----
    for (int l = 1; l < 3; l++) {
        int K2 = din[l] / 2, HC = HEADS * Cc[l];
        int nel = K2 * HC;
        split_pack_B_kernel<<<(nel + 255) / 256, 256>>>(
            (const float*)d_in[3 + 7 * l], p_wph + woffL[l], p_wpl + woffL[l], K2, HC);
        split_pack_B_kernel<<<(nel + 255) / 256, 256>>>(
            (const float*)d_in[4 + 7 * l], p_wph + woffR[l], p_wpl + woffR[l], K2, HC);
    }
    split_pack_B_kernel<<<(64 * 128 + 255) / 256, 256>>>(
        (const float*)d_in[24], p_wph + WOFF_AW1, p_wpl + WOFF_AW1, 64, 128);

    float* acts[3] = {p_a0, p_a1, p_a0};

    for (int l = 0; l < 3; l++) {
        int K2 = din[l] / 2;
        int C  = Cc[l];
        int HC = HEADS * C;
        int HC4 = HC / 4;
        int lg  = (HC4 == 128) ? 7 : (HC4 == 64 ? 6 : 5);
        const float* att = (const float*)d_in[5 + 7 * l];
        const float* bb  = (const float*)d_in[6 + 7 * l];
        const float* gw  = (const float*)d_in[7 + 7 * l];
        const float* gb  = (const float*)d_in[8 + 7 * l];
        const float* gm  = (const float*)d_in[9 + 7 * l];
        float* out = acts[l];

        if (l > 0) {
            dim3 gblk(2 * HC / 128, N / 128);
            bf16gemm_pre<<<gblk, 256, GEMM_SMEM>>>(p_xph, p_xpl,
                                        p_wph + woffL[l], p_wpl + woffL[l],
                                        p_wph + woffR[l], p_wpl + woffR[l],
                                        p_xl, p_xr, nullptr, 0, N, K2, HC);
        }

        int eblocks = (N * 32 + 255) / 256;
        if (C == 128)
            gat_edge_fused<4, 5><<<eblocks, 256>>>(
                (const float4*)p_xl, (const float4*)p_xr, (const float4*)att,
                p_ptr, p_csrc, (float4*)out, N);
        else if (C == 64)
            gat_edge_fused<2, 4><<<eblocks, 256>>>(
                (const float4*)p_xl, (const float4*)p_xr, (const float4*)att,
                p_ptr, p_csrc, (float4*)out, N);
        else
            gat_edge_fused<1, 3><<<eblocks, 256>>>(
                (const float4*)p_xl, (const float4*)p_xr, (const float4*)att,
                p_ptr, p_csrc, (float4*)out, N);

        fill_f_kernel<<<(2 * HC + 255) / 256, 256>>>(p_stats, 0.f, 2 * HC);
        colstats_kernel<<<(N + 63) / 64, 256>>>((const float4*)out, p_stats, N, HC4, lg);
        colscale_kernel<<<(HC + 255) / 256, 256>>>(p_stats, bb, gw, gb, gm,
                                                   p_colA, p_colS, N, HC);
        norm_relu_split_kernel<<<(N * HC4 + 255) / 256, 256>>>(
            (float4*)out, (const float4*)p_colA, (const float4*)p_colS,
            p_xph, p_xpl, N * HC4, HC4, (l == 2) ? 1 : 0);
    }

    // ---- Pooling ----
    const float* ab1 = (const float*)d_in[25];
    const float* aW2 = (const float*)d_in[26];
    const float* ab2 = (const float*)d_in[27];
    float* xfin = acts[2];

    dim3 hblk(1, N / 128);
    bf16gemm_pre<<<hblk, 256, GEMM_SMEM>>>(p_xph, p_xpl,
                                p_wph + WOFF_AW1, p_wpl + WOFF_AW1,
                                nullptr, nullptr,
                                p_hidden, nullptr, ab1, 1, N, 64, 128);
    gate_kernel<<<(N * 32 + 255) / 256, 256>>>((const float4*)p_hidden,
                                               (const float4*)aW2, ab2, p_gate, N);
    pool_kernel<<<NGRAPH, 128>>>(xfin, p_gate, batch, (float*)d_out, N);
}

// round 13
// speedup vs baseline: 1.0968x; 1.0968x over previous
#include <cuda_runtime.h>
#include <cuda_bf16.h>
#include <math.h>
#include <stdint.h>

// ---------------------------------------------------------------------------
// Problem constants
// ---------------------------------------------------------------------------
#define NMAX   16000
#define EMAX   256000
#define ETMAX  (EMAX + NMAX)
#define HEADS  4
#define MAXHC  512
#define NGRAPH 64
#define MAXK2  480

#define WOFF_L0L 0
#define WOFF_L0R 245760
#define WOFF_L1L 491520
#define WOFF_L1R 557056
#define WOFF_L2L 622592
#define WOFF_L2R 638976
#define WOFF_AW1 655360
#define WTOTAL   663552

// GEMM smem: 3 stages x 24576 bytes
#define STAGE_BYTES 24576
#define GEMM_SMEM   (3 * STAGE_BYTES)

// ---------------------------------------------------------------------------
// Static device scratch
// ---------------------------------------------------------------------------
__device__ float    g_xl   [NMAX * MAXHC];
__device__ float    g_xr   [NMAX * MAXHC];
__device__ float    g_act0 [NMAX * MAXHC];
__device__ float    g_act1 [NMAX * MAXHC];
__device__ float    g_stats[2 * MAXHC];
__device__ float    g_colA [MAXHC];
__device__ float    g_colS [MAXHC];
__device__ float    g_hidden[NMAX * 128];
__device__ float    g_gate [NMAX];
__device__ uint32_t g_xph  [NMAX * MAXK2];
__device__ uint32_t g_xpl  [NMAX * MAXK2];
__device__ uint32_t g_wph  [WTOTAL];
__device__ uint32_t g_wpl  [WTOTAL];
__device__ int      g_deg  [NMAX];
__device__ int      g_ptr  [NMAX + 1];
__device__ int      g_pos  [NMAX];
__device__ int      g_csrc [ETMAX];

// ---------------------------------------------------------------------------
// Helpers
// ---------------------------------------------------------------------------
__device__ __forceinline__ void packsplit(float x0, float x1,
                                          uint32_t& hi, uint32_t& lo) {
    __nv_bfloat16 h0 = __float2bfloat16_rn(x0);
    __nv_bfloat16 h1 = __float2bfloat16_rn(x1);
    float l0f = x0 - __bfloat162float(h0);
    float l1f = x1 - __bfloat162float(h1);
    __nv_bfloat16 l0 = __float2bfloat16_rn(l0f);
    __nv_bfloat16 l1 = __float2bfloat16_rn(l1f);
    __nv_bfloat162 hp = __halves2bfloat162(h0, h1);
    __nv_bfloat162 lp = __halves2bfloat162(l0, l1);
    hi = *reinterpret_cast<uint32_t*>(&hp);
    lo = *reinterpret_cast<uint32_t*>(&lp);
}

__global__ void fill_f_kernel(float* __restrict__ p, float v, int n) {
    int i = blockIdx.x * blockDim.x + threadIdx.x;
    if (i < n) p[i] = v;
}
__global__ void fill_i_kernel(int* __restrict__ p, int v, int n) {
    int i = blockIdx.x * blockDim.x + threadIdx.x;
    if (i < n) p[i] = v;
}

__global__ void split_pack_A_kernel(const float2* __restrict__ in,
                                    uint32_t* __restrict__ hi, uint32_t* __restrict__ lo,
                                    int n2) {
    int i = blockIdx.x * blockDim.x + threadIdx.x;
    if (i >= n2) return;
    float2 v = in[i];
    uint32_t h, l;
    packsplit(v.x, v.y, h, l);
    hi[i] = h; lo[i] = l;
}

// pack fp32 [K, HC] -> hi/lo uint32 in N-MAJOR layout [HC, K/2]
__global__ void split_pack_B_kernel(const float* __restrict__ W,
                                    uint32_t* __restrict__ hi, uint32_t* __restrict__ lo,
                                    int K2, int HC) {
    int i = blockIdx.x * blockDim.x + threadIdx.x;
    if (i >= K2 * HC) return;
    int n = i / K2, kp = i - n * K2;
    float x0 = W[(size_t)(2 * kp) * HC + n];
    float x1 = W[(size_t)(2 * kp + 1) * HC + n];
    uint32_t h, l;
    packsplit(x0, x1, h, l);
    hi[(size_t)n * K2 + kp] = h;
    lo[(size_t)n * K2 + kp] = l;
}

// ---------------------------------------------------------------------------
// CSR build over dst; stores gathered src per CSR slot.
// ---------------------------------------------------------------------------
__global__ void csr_count_kernel(const int* __restrict__ dst, int* __restrict__ deg,
                                 int E, int Nn) {
    int e = blockIdx.x * blockDim.x + threadIdx.x;
    int Et = E + Nn;
    if (e >= Et) return;
    int d = (e < E) ? dst[e] : (e - E);
    atomicAdd(&deg[d], 1);
}

__global__ void csr_scan_kernel(const int* __restrict__ deg, int* __restrict__ ptr,
                                int* __restrict__ pos, int n) {
    __shared__ int ss[1024];
    int t = threadIdx.x;
    int base = t * 16;
    int loc[16];
    int s = 0;
    #pragma unroll
    for (int i = 0; i < 16; i++) {
        int v = (base + i < n) ? deg[base + i] : 0;
        loc[i] = v; s += v;
    }
    ss[t] = s;
    __syncthreads();
    for (int off = 1; off < 1024; off <<= 1) {
        int v = (t >= off) ? ss[t - off] : 0;
        __syncthreads();
        ss[t] += v;
        __syncthreads();
    }
    int run = (t > 0) ? ss[t - 1] : 0;
    #pragma unroll
    for (int i = 0; i < 16; i++) {
        if (base + i < n) {
            ptr[base + i] = run;
            pos[base + i] = run;
            run += loc[i];
        }
    }
    if (t == 1023) ptr[n] = ss[1023];
}

__global__ void csr_scatter_kernel(const int* __restrict__ src, const int* __restrict__ dst,
                                   int* __restrict__ pos, int* __restrict__ csrc,
                                   int E, int Nn) {
    int e = blockIdx.x * blockDim.x + threadIdx.x;
    int Et = E + Nn;
    if (e >= Et) return;
    int d, s;
    if (e < E) { d = dst[e]; s = src[e]; } else { d = s = e - E; }
    int slot = atomicAdd(&pos[d], 1);
    csrc[slot] = s;
}

// ---------------------------------------------------------------------------
// bf16 3-term tensor-core GEMM: 3-stage cp.async ring + ldmatrix fragments.
// __launch_bounds__(256, 2) caps regs at 128 so 2 CTAs/SM fit (regfile).
// A: hi/lo uint32 [M, K2]; B: hi/lo uint32 N-MAJOR [HC, K2].
// Block 128x128x(8 k-pairs), 8 warps (2x4), warp tile 64x32, mma m16n8k16.
// Per-stage layout (byte offsets): AH +0, AL +6144, BH +12288, BL +18432.
// Row pitch 12 words (8 data + 4 pad) -> conflict-free ldmatrix.
// ---------------------------------------------------------------------------
__device__ __forceinline__ void mma_bf16(float* d, const uint32_t* a, const uint32_t* b) {
    asm volatile(
        "mma.sync.aligned.m16n8k16.row.col.f32.bf16.bf16.f32 "
        "{%0,%1,%2,%3}, {%4,%5,%6,%7}, {%8,%9}, {%0,%1,%2,%3};\n"
        : "+f"(d[0]), "+f"(d[1]), "+f"(d[2]), "+f"(d[3])
        : "r"(a[0]), "r"(a[1]), "r"(a[2]), "r"(a[3]), "r"(b[0]), "r"(b[1]));
}

#define LDSM4(r, a) asm volatile( \
    "ldmatrix.sync.aligned.m8n8.x4.shared.b16 {%0,%1,%2,%3}, [%4];" \
    : "=r"((r)[0]), "=r"((r)[1]), "=r"((r)[2]), "=r"((r)[3]) : "r"(a))
#define LDSM2(r0, r1, a) asm volatile( \
    "ldmatrix.sync.aligned.m8n8.x2.shared.b16 {%0,%1}, [%2];" \
    : "=r"(r0), "=r"(r1) : "r"(a))
#define CPA16(s, g) asm volatile( \
    "cp.async.cg.shared.global [%0], [%1], 16;" :: "r"(s), "l"(g))
#define CPCOMMIT() asm volatile("cp.async.commit_group;")
#define CPWAIT0()  asm volatile("cp.async.wait_group 0;")
#define CPWAIT1()  asm volatile("cp.async.wait_group 1;")

__global__ void __launch_bounds__(256, 2)
bf16gemm_pre(const uint32_t* __restrict__ XH, const uint32_t* __restrict__ XL,
             const uint32_t* __restrict__ WH0, const uint32_t* __restrict__ WL0,
             const uint32_t* __restrict__ WH1, const uint32_t* __restrict__ WL1,
             float* __restrict__ out0, float* __restrict__ out1,
             const float* __restrict__ bias, int relu,
             int M, int K2, int HC) {
    extern __shared__ uint32_t S[];
    uint32_t sbase = (uint32_t)__cvta_generic_to_shared(S);

    const int t  = threadIdx.x;
    const int bm = blockIdx.y * 128;
    int bn = blockIdx.x * 128;

    const uint32_t* WH = WH0;
    const uint32_t* WL = WL0;
    float* out = out0;
    int col0 = bn;
    if (WH1 != nullptr && bn >= HC) { WH = WH1; WL = WL1; out = out1; col0 = bn - HC; }

    // cp.async loaders: thread -> (row = t>>1, 16B seg = t&1)
    const int lrow = t >> 1;
    const int lseg = t & 1;
    const uint32_t* ApH = XH + (size_t)(bm + lrow) * K2 + lseg * 4;
    const uint32_t* ApL = XL + (size_t)(bm + lrow) * K2 + lseg * 4;
    const uint32_t* BpH = WH + (size_t)(col0 + lrow) * K2 + lseg * 4;
    const uint32_t* BpL = WL + (size_t)(col0 + lrow) * K2 + lseg * 4;
    const uint32_t sst = sbase + (lrow * 12 + lseg * 4) * 4;   // AH intra-stage addr

    // warp/lane geometry
    const int wA   = t >> 5;
    const int lane = t & 31;
    const int m0w = (wA >> 2) * 64;
    const int n0w = (wA & 3) * 32;
    const int tq   = lane & 3;
    const int trow = lane >> 2;

    // ldmatrix intra-stage fragment addresses (bytes)
    const uint32_t afo = sbase +
        ((m0w + (lane & 7) + ((lane >> 3) & 1) * 8) * 12 + ((lane >> 4) & 1) * 4) * 4;
    const uint32_t bfo = sbase + 12288 +
        ((n0w + (lane & 7)) * 12 + ((lane >> 3) & 1) * 4) * 4;

    float acc[4][4][4];
    #pragma unroll
    for (int i = 0; i < 4; i++)
        #pragma unroll
        for (int j = 0; j < 4; j++)
            #pragma unroll
            for (int r = 0; r < 4; r++) acc[i][j][r] = 0.f;

    const int nt = K2 >> 3;

    // prologue: tiles 0 and 1 into stages 0 and 1
    {
        CPA16(sst,          ApH);
        CPA16(sst + 6144,   ApL);
        CPA16(sst + 12288,  BpH);
        CPA16(sst + 18432,  BpL);
        CPCOMMIT();
        if (1 < nt) {
            uint32_t o = STAGE_BYTES;
            CPA16(sst + o,          ApH + 8);
            CPA16(sst + o + 6144,   ApL + 8);
            CPA16(sst + o + 12288,  BpH + 8);
            CPA16(sst + o + 18432,  BpL + 8);
            CPCOMMIT();
        }
    }

    int stage = 0;           // stage of tile `it`
    int wstage = (nt >= 2) ? 2 : 1;   // next stage to write
    for (int it = 0; it < nt; it++) {
        if (it + 1 < nt) { CPWAIT1(); } else { CPWAIT0(); }
        __syncthreads();
        if (it + 2 < nt) {
            int p0 = (it + 2) << 3;
            uint32_t o = (uint32_t)wstage * STAGE_BYTES;
            CPA16(sst + o,          ApH + p0);
            CPA16(sst + o + 6144,   ApL + p0);
            CPA16(sst + o + 12288,  BpH + p0);
            CPA16(sst + o + 18432,  BpL + p0);
            CPCOMMIT();
            wstage = (wstage == 2) ? 0 : wstage + 1;
        }

        uint32_t ob = (uint32_t)stage * STAGE_BYTES;
        uint32_t aH[4][4], aL[4][4];
        #pragma unroll
        for (int i = 0; i < 4; i++) {
            LDSM4(aH[i], afo + ob + i * 768);
            LDSM4(aL[i], afo + ob + i * 768 + 6144);
        }
        #pragma unroll
        for (int j = 0; j < 4; j++) {
            uint32_t bH[2], bL[2];
            LDSM2(bH[0], bH[1], bfo + ob + j * 384);
            LDSM2(bL[0], bL[1], bfo + ob + j * 384 + 6144);
            #pragma unroll
            for (int i = 0; i < 4; i++) {
                mma_bf16(acc[i][j], aH[i], bH);
                mma_bf16(acc[i][j], aH[i], bL);
                mma_bf16(acc[i][j], aL[i], bH);
            }
        }
        stage = (stage == 2) ? 0 : stage + 1;
    }

    // epilogue
    #pragma unroll
    for (int i = 0; i < 4; i++) {
        int gr0 = bm + m0w + i * 16 + trow;
        #pragma unroll
        for (int j = 0; j < 4; j++) {
            int gc = col0 + n0w + j * 8 + tq * 2;
            float2 v0 = make_float2(acc[i][j][0], acc[i][j][1]);
            float2 v1 = make_float2(acc[i][j][2], acc[i][j][3]);
            if (bias) {
                float b0 = bias[gc], b1 = bias[gc + 1];
                v0.x += b0; v0.y += b1;
                v1.x += b0; v1.y += b1;
            }
            if (relu) {
                v0.x = fmaxf(v0.x, 0.f); v0.y = fmaxf(v0.y, 0.f);
                v1.x = fmaxf(v1.x, 0.f); v1.y = fmaxf(v1.y, 0.f);
            }
            *(float2*)&out[(size_t)gr0 * HC + gc]       = v0;
            *(float2*)&out[(size_t)(gr0 + 8) * HC + gc] = v1;
        }
    }
}

// ---------------------------------------------------------------------------
// Fused GATv2 edge phase (unconditional online-softmax update).
// ---------------------------------------------------------------------------
template <int NV4, int CSH>
__global__ void gat_edge_fused(const float4* __restrict__ xl4,
                               const float4* __restrict__ xr4,
                               const float4* __restrict__ att4,
                               const int* __restrict__ ptr,
                               const int* __restrict__ csrc,
                               float4* __restrict__ out4, int Nn) {
    int n    = (blockIdx.x * blockDim.x + threadIdx.x) >> 5;
    int lane = threadIdx.x & 31;
    if (n >= Nn) return;
    const int HC4 = NV4 * 32;

    float4 xr[NV4], at[NV4];
    #pragma unroll
    for (int r = 0; r < NV4; r++) {
        xr[r] = xr4[(size_t)n * HC4 + r * 32 + lane];
        at[r] = att4[r * 32 + lane];
    }

    float m[NV4], z[NV4];
    float4 acc[NV4];
    #pragma unroll
    for (int r = 0; r < NV4; r++) {
        m[r] = -1e30f; z[r] = 0.f;
        acc[r] = make_float4(0.f, 0.f, 0.f, 0.f);
    }

    int beg = ptr[n], end = ptr[n + 1];
    if (beg >= end) return;

    float4 xv[NV4];
    {
        int s = csrc[beg];
        #pragma unroll
        for (int r = 0; r < NV4; r++)
            xv[r] = xl4[(size_t)s * HC4 + r * 32 + lane];
    }

    for (int i = beg; i < end; i++) {
        float4 xn[NV4];
        bool more = (i + 1 < end);
        if (more) {
            int s2 = csrc[i + 1];
            #pragma unroll
            for (int r = 0; r < NV4; r++)
                xn[r] = xl4[(size_t)s2 * HC4 + r * 32 + lane];
        }

        float p[NV4];
        #pragma unroll
        for (int r = 0; r < NV4; r++) {
            float v, s = 0.f;
            v = xv[r].x + xr[r].x; v = (v > 0.f) ? v : 0.2f * v; s += at[r].x * v;
            v = xv[r].y + xr[r].y; v = (v > 0.f) ? v : 0.2f * v; s += at[r].y * v;
            v = xv[r].z + xr[r].z; v = (v > 0.f) ? v : 0.2f * v; s += at[r].z * v;
            v = xv[r].w + xr[r].w; v = (v > 0.f) ? v : 0.2f * v; s += at[r].w * v;
            p[r] = s;
        }
        #pragma unroll
        for (int r = 0; r < NV4; r++) {
            #pragma unroll
            for (int off = (1 << CSH) >> 1; off > 0; off >>= 1)
                p[r] += __shfl_xor_sync(0xffffffffu, p[r], off);
        }
        #pragma unroll
        for (int r = 0; r < NV4; r++) {
            float mn = fmaxf(m[r], p[r]);
            float sc = expf(m[r] - mn);
            float pe = expf(p[r] - mn);
            z[r] = z[r] * sc + pe;
            m[r] = mn;
            acc[r].x = acc[r].x * sc + pe * xv[r].x;
            acc[r].y = acc[r].y * sc + pe * xv[r].y;
            acc[r].z = acc[r].z * sc + pe * xv[r].z;
            acc[r].w = acc[r].w * sc + pe * xv[r].w;
        }
        if (more) {
            #pragma unroll
            for (int r = 0; r < NV4; r++) xv[r] = xn[r];
        }
    }

    #pragma unroll
    for (int r = 0; r < NV4; r++) {
        float inv = 1.f / (z[r] + 1e-16f);
        float4 o;
        o.x = acc[r].x * inv; o.y = acc[r].y * inv;
        o.z = acc[r].z * inv; o.w = acc[r].w * inv;
        out4[(size_t)n * HC4 + r * 32 + lane] = o;
    }
}

// ---------------------------------------------------------------------------
// GraphNorm
// ---------------------------------------------------------------------------
__global__ void colstats_kernel(const float4* __restrict__ x4, float* __restrict__ stats,
                                int Nn, int Cn4, int lg) {
    int r0   = blockIdx.x * 64;
    int rend = min(r0 + 64, Nn);
    int tx  = threadIdx.x & (Cn4 - 1);
    int ty  = threadIdx.x >> lg;
    int nty = 256 >> lg;
    float4 s = make_float4(0.f, 0.f, 0.f, 0.f);
    float4 q = make_float4(0.f, 0.f, 0.f, 0.f);
    for (int r = r0 + ty; r < rend; r += nty) {
        float4 v = x4[(size_t)r * Cn4 + tx];
        s.x += v.x; s.y += v.y; s.z += v.z; s.w += v.w;
        q.x += v.x * v.x; q.y += v.y * v.y; q.z += v.z * v.z; q.w += v.w * v.w;
    }
    int Cn = Cn4 * 4;
    int c = tx * 4;
    atomicAdd(&stats[c + 0], s.x); atomicAdd(&stats[c + 1], s.y);
    atomicAdd(&stats[c + 2], s.z); atomicAdd(&stats[c + 3], s.w);
    atomicAdd(&stats[Cn + c + 0], q.x); atomicAdd(&stats[Cn + c + 1], q.y);
    atomicAdd(&stats[Cn + c + 2], q.z); atomicAdd(&stats[Cn + c + 3], q.w);
}

__global__ void colscale_kernel(const float* __restrict__ stats,
                                const float* __restrict__ bias,
                                const float* __restrict__ gw, const float* __restrict__ gb,
                                const float* __restrict__ gm,
                                float* __restrict__ colA, float* __restrict__ colS,
                                int Nn, int Cn) {
    int c = blockIdx.x * blockDim.x + threadIdx.x;
    if (c >= Cn) return;
    float invN = 1.0f / (float)Nn;
    float ma = stats[c] * invN;
    float q  = stats[Cn + c] * invN;
    float b  = bias[c];
    float mx = ma + b;
    float tt = b - gm[c] * mx;
    float var = q + 2.f * tt * ma + tt * tt;
    var = fmaxf(var, 0.f);
    float A = gw[c] * rsqrtf(var + 1e-5f);
    colA[c] = A;
    colS[c] = A * tt + gb[c];
}

__global__ void norm_relu_split_kernel(float4* __restrict__ x4,
                                       const float4* __restrict__ colA4,
                                       const float4* __restrict__ colS4,
                                       uint32_t* __restrict__ xph,
                                       uint32_t* __restrict__ xpl,
                                       int total4, int Cn4, int wb) {
    int i = blockIdx.x * blockDim.x + threadIdx.x;
    if (i >= total4) return;
    int c = i % Cn4;
    float4 v = x4[i];
    float4 A = colA4[c];
    float4 S = colS4[c];
    v.x = fmaxf(A.x * v.x + S.x, 0.f);
    v.y = fmaxf(A.y * v.y + S.y, 0.f);
    v.z = fmaxf(A.z * v.z + S.z, 0.f);
    v.w = fmaxf(A.w * v.w + S.w, 0.f);
    if (wb) x4[i] = v;
    uint32_t h0, l0, h1, l1;
    packsplit(v.x, v.y, h0, l0);
    packsplit(v.z, v.w, h1, l1);
    xph[2 * i]     = h0; xph[2 * i + 1] = h1;
    xpl[2 * i]     = l0; xpl[2 * i + 1] = l1;
}

// ---------------------------------------------------------------------------
// Pooling
// ---------------------------------------------------------------------------
__global__ void gate_kernel(const float4* __restrict__ hidden4, const float4* __restrict__ aW24,
                            const float* __restrict__ ab2, float* __restrict__ gate, int Nn) {
    int gw   = (blockIdx.x * blockDim.x + threadIdx.x) >> 5;
    int lane = threadIdx.x & 31;
    if (gw >= Nn) return;
    float4 h = hidden4[(size_t)gw * 32 + lane];
    float4 w = aW24[lane];
    float acc = h.x * w.x + h.y * w.y + h.z * w.z + h.w * w.w;
    #pragma unroll
    for (int o = 16; o > 0; o >>= 1) acc += __shfl_down_sync(0xffffffffu, acc, o);
    if (lane == 0) gate[gw] = acc + ab2[0];
}

__device__ __forceinline__ int lower_bound_dev(const int* __restrict__ a, int n, int v) {
    int lo = 0, hi = n;
    while (lo < hi) {
        int mid = (lo + hi) >> 1;
        if (a[mid] < v) lo = mid + 1; else hi = mid;
    }
    return lo;
}

__global__ void pool_kernel(const float* __restrict__ x, const float* __restrict__ gate,
                            const int* __restrict__ batch, float* __restrict__ out, int Nn) {
    __shared__ float red[128];
    __shared__ float wbuf[128];
    int b = blockIdx.x;
    int t = threadIdx.x;
    int beg = lower_bound_dev(batch, Nn, b);
    int end = lower_bound_dev(batch, Nn, b + 1);

    float mx = -1e30f;
    for (int n = beg + t; n < end; n += 128) mx = fmaxf(mx, gate[n]);
    red[t] = mx; __syncthreads();
    for (int o = 64; o > 0; o >>= 1) {
        if (t < o) red[t] = fmaxf(red[t], red[t + o]);
        __syncthreads();
    }
    float m = red[0];
    if (m < -1e29f) m = 0.f;
    __syncthreads();

    float zs = 0.f;
    for (int n = beg + t; n < end; n += 128) zs += expf(gate[n] - m);
    red[t] = zs; __syncthreads();
    for (int o = 64; o > 0; o >>= 1) {
        if (t < o) red[t] += red[t + o];
        __syncthreads();
    }
    float inv = 1.f / (red[0] + 1e-16f);
    __syncthreads();

    float acc = 0.f;
    for (int base = beg; base < end; base += 128) {
        int n = base + t;
        wbuf[t] = (n < end) ? expf(gate[n] - m) * inv : 0.f;
        __syncthreads();
        int cnt = min(128, end - base);
        for (int k = 0; k < cnt; k++)
            acc += wbuf[k] * x[(size_t)(base + k) * 128 + t];
        __syncthreads();
    }
    out[b * 128 + t] = acc;
}

// ---------------------------------------------------------------------------
// Host orchestration
// ---------------------------------------------------------------------------
extern "C" void kernel_launch(void* const* d_in, const int* in_sizes, int n_in,
                              void* d_out, int out_size) {
    const float* x0    = (const float*)d_in[0];
    const int*   ei    = (const int*)d_in[1];
    const int*   batch = (const int*)d_in[2];

    int N = in_sizes[0] / 960;
    int E = in_sizes[1] / 2;
    const int* src = ei;
    const int* dst = ei + E;
    int Et = E + N;

    // Unconditional every call (no static guard): idempotent host-side call.
    cudaFuncSetAttribute(bf16gemm_pre,
                         cudaFuncAttributeMaxDynamicSharedMemorySize, GEMM_SMEM);

    float *p_xl, *p_xr, *p_a0, *p_a1, *p_stats, *p_colA, *p_colS, *p_hidden, *p_gate;
    uint32_t *p_xph, *p_xpl, *p_wph, *p_wpl;
    int *p_deg, *p_ptr, *p_pos, *p_csrc;
    cudaGetSymbolAddress((void**)&p_xl,    g_xl);
    cudaGetSymbolAddress((void**)&p_xr,    g_xr);
    cudaGetSymbolAddress((void**)&p_a0,    g_act0);
    cudaGetSymbolAddress((void**)&p_a1,    g_act1);
    cudaGetSymbolAddress((void**)&p_stats, g_stats);
    cudaGetSymbolAddress((void**)&p_colA,  g_colA);
    cudaGetSymbolAddress((void**)&p_colS,  g_colS);
    cudaGetSymbolAddress((void**)&p_hidden,g_hidden);
    cudaGetSymbolAddress((void**)&p_gate,  g_gate);
    cudaGetSymbolAddress((void**)&p_xph,   g_xph);
    cudaGetSymbolAddress((void**)&p_xpl,   g_xpl);
    cudaGetSymbolAddress((void**)&p_wph,   g_wph);
    cudaGetSymbolAddress((void**)&p_wpl,   g_wpl);
    cudaGetSymbolAddress((void**)&p_deg,   g_deg);
    cudaGetSymbolAddress((void**)&p_ptr,   g_ptr);
    cudaGetSymbolAddress((void**)&p_pos,   g_pos);
    cudaGetSymbolAddress((void**)&p_csrc,  g_csrc);

    const int woffL[3] = {WOFF_L0L, WOFF_L1L, WOFF_L2L};
    const int woffR[3] = {WOFF_L0R, WOFF_L1R, WOFF_L2R};
    const int din[3] = {960, 512, 256};
    const int Cc[3]  = {128, 64, 32};

    // ---- Launches 1-3: layer-0 operand packs (so launch 4 = GEMM, profiled) ----
    {
        int K2 = 480, HC = 512, nel = K2 * HC;
        split_pack_B_kernel<<<(nel + 255) / 256, 256>>>(
            (const float*)d_in[3], p_wph + WOFF_L0L, p_wpl + WOFF_L0L, K2, HC);
        split_pack_B_kernel<<<(nel + 255) / 256, 256>>>(
            (const float*)d_in[4], p_wph + WOFF_L0R, p_wpl + WOFF_L0R, K2, HC);
    }
    split_pack_A_kernel<<<(N * 480 + 255) / 256, 256>>>(
        (const float2*)x0, p_xph, p_xpl, N * 480);

    // ---- Launch 4: layer-0 dual GEMM (ncu-profiled) ----
    {
        dim3 gblk(2 * 512 / 128, N / 128);
        bf16gemm_pre<<<gblk, 256, GEMM_SMEM>>>(p_xph, p_xpl,
                                    p_wph + WOFF_L0L, p_wpl + WOFF_L0L,
                                    p_wph + WOFF_L0R, p_wpl + WOFF_L0R,
                                    p_xl, p_xr, nullptr, 0, N, 480, 512);
    }

    // ---- CSR build ----
    fill_i_kernel<<<(N + 255) / 256, 256>>>(p_deg, 0, N);
    csr_count_kernel<<<(Et + 255) / 256, 256>>>(dst, p_deg, E, N);
    csr_scan_kernel<<<1, 1024>>>(p_deg, p_ptr, p_pos, N);
    csr_scatter_kernel<<<(Et + 255) / 256, 256>>>(src, dst, p_pos, p_csrc, E, N);

    // ---- Remaining weight packs ----
    for (int l = 1; l < 3; l++) {
        int K2 = din[l] / 2, HC = HEADS * Cc[l];
        int nel = K2 * HC;
        split_pack_B_kernel<<<(nel + 255) / 256, 256>>>(
            (const float*)d_in[3 + 7 * l], p_wph + woffL[l], p_wpl + woffL[l], K2, HC);
        split_pack_B_kernel<<<(nel + 255) / 256, 256>>>(
            (const float*)d_in[4 + 7 * l], p_wph + woffR[l], p_wpl + woffR[l], K2, HC);
    }
    split_pack_B_kernel<<<(64 * 128 + 255) / 256, 256>>>(
        (const float*)d_in[24], p_wph + WOFF_AW1, p_wpl + WOFF_AW1, 64, 128);

    float* acts[3] = {p_a0, p_a1, p_a0};

    for (int l = 0; l < 3; l++) {
        int K2 = din[l] / 2;
        int C  = Cc[l];
        int HC = HEADS * C;
        int HC4 = HC / 4;
        int lg  = (HC4 == 128) ? 7 : (HC4 == 64 ? 6 : 5);
        const float* att = (const float*)d_in[5 + 7 * l];
        const float* bb  = (const float*)d_in[6 + 7 * l];
        const float* gw  = (const float*)d_in[7 + 7 * l];
        const float* gb  = (const float*)d_in[8 + 7 * l];
        const float* gm  = (const float*)d_in[9 + 7 * l];
        float* out = acts[l];

        if (l > 0) {
            dim3 gblk(2 * HC / 128, N / 128);
            bf16gemm_pre<<<gblk, 256, GEMM_SMEM>>>(p_xph, p_xpl,
                                        p_wph + woffL[l], p_wpl + woffL[l],
                                        p_wph + woffR[l], p_wpl + woffR[l],
                                        p_xl, p_xr, nullptr, 0, N, K2, HC);
        }

        int eblocks = (N * 32 + 255) / 256;
        if (C == 128)
            gat_edge_fused<4, 5><<<eblocks, 256>>>(
                (const float4*)p_xl, (const float4*)p_xr, (const float4*)att,
                p_ptr, p_csrc, (float4*)out, N);
        else if (C == 64)
            gat_edge_fused<2, 4><<<eblocks, 256>>>(
                (const float4*)p_xl, (const float4*)p_xr, (const float4*)att,
                p_ptr, p_csrc, (float4*)out, N);
        else
            gat_edge_fused<1, 3><<<eblocks, 256>>>(
                (const float4*)p_xl, (const float4*)p_xr, (const float4*)att,
                p_ptr, p_csrc, (float4*)out, N);

        fill_f_kernel<<<(2 * HC + 255) / 256, 256>>>(p_stats, 0.f, 2 * HC);
        colstats_kernel<<<(N + 63) / 64, 256>>>((const float4*)out, p_stats, N, HC4, lg);
        colscale_kernel<<<(HC + 255) / 256, 256>>>(p_stats, bb, gw, gb, gm,
                                                   p_colA, p_colS, N, HC);
        norm_relu_split_kernel<<<(N * HC4 + 255) / 256, 256>>>(
            (float4*)out, (const float4*)p_colA, (const float4*)p_colS,
            p_xph, p_xpl, N * HC4, HC4, (l == 2) ? 1 : 0);
    }

    // ---- Pooling ----
    const float* ab1 = (const float*)d_in[25];
    const float* aW2 = (const float*)d_in[26];
    const float* ab2 = (const float*)d_in[27];
    float* xfin = acts[2];

    dim3 hblk(1, N / 128);
    bf16gemm_pre<<<hblk, 256, GEMM_SMEM>>>(p_xph, p_xpl,
                                p_wph + WOFF_AW1, p_wpl + WOFF_AW1,
                                nullptr, nullptr,
                                p_hidden, nullptr, ab1, 1, N, 64, 128);
    gate_kernel<<<(N * 32 + 255) / 256, 256>>>((const float4*)p_hidden,
                                               (const float4*)aW2, ab2, p_gate, N);
    pool_kernel<<<NGRAPH, 128>>>(xfin, p_gate, batch, (float*)d_out, N);
}

// round 14
// speedup vs baseline: 1.1192x; 1.0205x over previous
#include <cuda_runtime.h>
#include <cuda_bf16.h>
#include <math.h>
#include <stdint.h>

// ---------------------------------------------------------------------------
// Problem constants
// ---------------------------------------------------------------------------
#define NMAX   16000
#define EMAX   256000
#define ETMAX  (EMAX + NMAX)
#define HEADS  4
#define MAXHC  512
#define NGRAPH 64
#define MAXK2  480

#define WOFF_L0L 0
#define WOFF_L0R 245760
#define WOFF_L1L 491520
#define WOFF_L1R 557056
#define WOFF_L2L 622592
#define WOFF_L2R 638976
#define WOFF_AW1 655360
#define WTOTAL   663552

// ---------------------------------------------------------------------------
// Static device scratch
// ---------------------------------------------------------------------------
__device__ float    g_xl   [NMAX * MAXHC];
__device__ float    g_xr   [NMAX * MAXHC];
__device__ float    g_act0 [NMAX * MAXHC];
__device__ float    g_act1 [NMAX * MAXHC];
__device__ float    g_stats[2 * MAXHC];
__device__ float    g_colA [MAXHC];
__device__ float    g_colS [MAXHC];
__device__ float    g_hidden[NMAX * 128];
__device__ float    g_gate [NMAX];
__device__ uint32_t g_xph  [NMAX * MAXK2];
__device__ uint32_t g_xpl  [NMAX * MAXK2];
__device__ uint32_t g_wph  [WTOTAL];
__device__ uint32_t g_wpl  [WTOTAL];
__device__ int      g_deg  [NMAX];
__device__ int      g_ptr  [NMAX + 1];
__device__ int      g_pos  [NMAX];
__device__ int      g_csrc [ETMAX];

// ---------------------------------------------------------------------------
// Helpers
// ---------------------------------------------------------------------------
__device__ __forceinline__ void packsplit(float x0, float x1,
                                          uint32_t& hi, uint32_t& lo) {
    __nv_bfloat16 h0 = __float2bfloat16_rn(x0);
    __nv_bfloat16 h1 = __float2bfloat16_rn(x1);
    float l0f = x0 - __bfloat162float(h0);
    float l1f = x1 - __bfloat162float(h1);
    __nv_bfloat16 l0 = __float2bfloat16_rn(l0f);
    __nv_bfloat16 l1 = __float2bfloat16_rn(l1f);
    __nv_bfloat162 hp = __halves2bfloat162(h0, h1);
    __nv_bfloat162 lp = __halves2bfloat162(l0, l1);
    hi = *reinterpret_cast<uint32_t*>(&hp);
    lo = *reinterpret_cast<uint32_t*>(&lp);
}

__global__ void fill_f_kernel(float* __restrict__ p, float v, int n) {
    int i = blockIdx.x * blockDim.x + threadIdx.x;
    if (i < n) p[i] = v;
}
__global__ void fill_i_kernel(int* __restrict__ p, int v, int n) {
    int i = blockIdx.x * blockDim.x + threadIdx.x;
    if (i < n) p[i] = v;
}

__global__ void split_pack_A_kernel(const float2* __restrict__ in,
                                    uint32_t* __restrict__ hi, uint32_t* __restrict__ lo,
                                    int n2) {
    int i = blockIdx.x * blockDim.x + threadIdx.x;
    if (i >= n2) return;
    float2 v = in[i];
    uint32_t h, l;
    packsplit(v.x, v.y, h, l);
    hi[i] = h; lo[i] = l;
}

// pack fp32 [K, HC] -> hi/lo uint32 in N-MAJOR layout [HC, K/2]
__global__ void split_pack_B_kernel(const float* __restrict__ W,
                                    uint32_t* __restrict__ hi, uint32_t* __restrict__ lo,
                                    int K2, int HC) {
    int i = blockIdx.x * blockDim.x + threadIdx.x;
    if (i >= K2 * HC) return;
    int n = i / K2, kp = i - n * K2;
    float x0 = W[(size_t)(2 * kp) * HC + n];
    float x1 = W[(size_t)(2 * kp + 1) * HC + n];
    uint32_t h, l;
    packsplit(x0, x1, h, l);
    hi[(size_t)n * K2 + kp] = h;
    lo[(size_t)n * K2 + kp] = l;
}

// ---------------------------------------------------------------------------
// CSR build over dst; stores gathered src per CSR slot.
// ---------------------------------------------------------------------------
__global__ void csr_count_kernel(const int* __restrict__ dst, int* __restrict__ deg,
                                 int E, int Nn) {
    int e = blockIdx.x * blockDim.x + threadIdx.x;
    int Et = E + Nn;
    if (e >= Et) return;
    int d = (e < E) ? dst[e] : (e - E);
    atomicAdd(&deg[d], 1);
}

__global__ void csr_scan_kernel(const int* __restrict__ deg, int* __restrict__ ptr,
                                int* __restrict__ pos, int n) {
    __shared__ int ss[1024];
    int t = threadIdx.x;
    int base = t * 16;
    int loc[16];
    int s = 0;
    #pragma unroll
    for (int i = 0; i < 16; i++) {
        int v = (base + i < n) ? deg[base + i] : 0;
        loc[i] = v; s += v;
    }
    ss[t] = s;
    __syncthreads();
    for (int off = 1; off < 1024; off <<= 1) {
        int v = (t >= off) ? ss[t - off] : 0;
        __syncthreads();
        ss[t] += v;
        __syncthreads();
    }
    int run = (t > 0) ? ss[t - 1] : 0;
    #pragma unroll
    for (int i = 0; i < 16; i++) {
        if (base + i < n) {
            ptr[base + i] = run;
            pos[base + i] = run;
            run += loc[i];
        }
    }
    if (t == 1023) ptr[n] = ss[1023];
}

__global__ void csr_scatter_kernel(const int* __restrict__ src, const int* __restrict__ dst,
                                   int* __restrict__ pos, int* __restrict__ csrc,
                                   int E, int Nn) {
    int e = blockIdx.x * blockDim.x + threadIdx.x;
    int Et = E + Nn;
    if (e >= Et) return;
    int d, s;
    if (e < E) { d = dst[e]; s = src[e]; } else { d = s = e - E; }
    int slot = atomicAdd(&pos[d], 1);
    csrc[slot] = s;
}

// ---------------------------------------------------------------------------
// bf16 3-term tensor-core GEMM (R10 version, verbatim): 2-stage cp.async +
// ldmatrix. A: hi/lo uint32 [M, K2]; B: hi/lo uint32 N-MAJOR [HC, K2].
// Block 128x128x(8 k-pairs), 8 warps (2x4), warp tile 64x32, mma m16n8k16.
// SMEM: one array S, row pitch 12 words; AH(b)=b*1536w, AL=3072w+b*1536w,
// BH=6144w+b*1536w, BL=9216w+b*1536w. Total 12288 words = 48KB.
// ---------------------------------------------------------------------------
__device__ __forceinline__ void mma_bf16(float* d, const uint32_t* a, const uint32_t* b) {
    asm volatile(
        "mma.sync.aligned.m16n8k16.row.col.f32.bf16.bf16.f32 "
        "{%0,%1,%2,%3}, {%4,%5,%6,%7}, {%8,%9}, {%0,%1,%2,%3};\n"
        : "+f"(d[0]), "+f"(d[1]), "+f"(d[2]), "+f"(d[3])
        : "r"(a[0]), "r"(a[1]), "r"(a[2]), "r"(a[3]), "r"(b[0]), "r"(b[1]));
}

#define LDSM4(r, a) asm volatile( \
    "ldmatrix.sync.aligned.m8n8.x4.shared.b16 {%0,%1,%2,%3}, [%4];" \
    : "=r"((r)[0]), "=r"((r)[1]), "=r"((r)[2]), "=r"((r)[3]) : "r"(a))
#define LDSM2(r0, r1, a) asm volatile( \
    "ldmatrix.sync.aligned.m8n8.x2.shared.b16 {%0,%1}, [%2];" \
    : "=r"(r0), "=r"(r1) : "r"(a))
#define CPA16(s, g) asm volatile( \
    "cp.async.cg.shared.global [%0], [%1], 16;" :: "r"(s), "l"(g))
#define CPCOMMIT() asm volatile("cp.async.commit_group;")
#define CPWAIT0()  asm volatile("cp.async.wait_group 0;")

__global__ void __launch_bounds__(256)
bf16gemm_pre(const uint32_t* __restrict__ XH, const uint32_t* __restrict__ XL,
             const uint32_t* __restrict__ WH0, const uint32_t* __restrict__ WL0,
             const uint32_t* __restrict__ WH1, const uint32_t* __restrict__ WL1,
             float* __restrict__ out0, float* __restrict__ out1,
             const float* __restrict__ bias, int relu,
             int M, int K2, int HC) {
    __shared__ uint32_t S[12288];
    uint32_t sbase = (uint32_t)__cvta_generic_to_shared(S);

    const int t  = threadIdx.x;
    const int bm = blockIdx.y * 128;
    int bn = blockIdx.x * 128;

    const uint32_t* WH = WH0;
    const uint32_t* WL = WL0;
    float* out = out0;
    int col0 = bn;
    if (WH1 != nullptr && bn >= HC) { WH = WH1; WL = WL1; out = out1; col0 = bn - HC; }

    const int lrow = t >> 1;
    const int lseg = t & 1;
    const uint32_t* ApH = XH + (size_t)(bm + lrow) * K2 + lseg * 4;
    const uint32_t* ApL = XL + (size_t)(bm + lrow) * K2 + lseg * 4;
    const uint32_t* BpH = WH + (size_t)(col0 + lrow) * K2 + lseg * 4;
    const uint32_t* BpL = WL + (size_t)(col0 + lrow) * K2 + lseg * 4;
    const uint32_t sst = sbase + (lrow * 12 + lseg * 4) * 4;

    const int wA   = t >> 5;
    const int lane = t & 31;
    const int m0w = (wA >> 2) * 64;
    const int n0w = (wA & 3) * 32;
    const int tq   = lane & 3;
    const int trow = lane >> 2;

    const uint32_t afo = sbase +
        ((m0w + (lane & 7) + ((lane >> 3) & 1) * 8) * 12 + ((lane >> 4) & 1) * 4) * 4;
    const uint32_t bfo = sbase + 24576 +
        ((n0w + (lane & 7)) * 12 + ((lane >> 3) & 1) * 4) * 4;

    float acc[4][4][4];
    #pragma unroll
    for (int i = 0; i < 4; i++)
        #pragma unroll
        for (int j = 0; j < 4; j++)
            #pragma unroll
            for (int r = 0; r < 4; r++) acc[i][j][r] = 0.f;

    CPA16(sst,          ApH);
    CPA16(sst + 12288,  ApL);
    CPA16(sst + 24576,  BpH);
    CPA16(sst + 36864,  BpL);
    CPCOMMIT();

    const int nt = K2 >> 3;
    for (int it = 0; it < nt; it++) {
        CPWAIT0();
        __syncthreads();
        if (it + 1 < nt) {
            int p0 = (it + 1) << 3;
            uint32_t o = ((it + 1) & 1) * 6144;
            CPA16(sst + o,          ApH + p0);
            CPA16(sst + o + 12288,  ApL + p0);
            CPA16(sst + o + 24576,  BpH + p0);
            CPA16(sst + o + 36864,  BpL + p0);
            CPCOMMIT();
        }

        uint32_t ob = (it & 1) * 6144;
        uint32_t aH[4][4], aL[4][4];
        #pragma unroll
        for (int i = 0; i < 4; i++) {
            LDSM4(aH[i], afo + ob + i * 768);
            LDSM4(aL[i], afo + ob + i * 768 + 12288);
        }
        #pragma unroll
        for (int j = 0; j < 4; j++) {
            uint32_t bH[2], bL[2];
            LDSM2(bH[0], bH[1], bfo + ob + j * 384);
            LDSM2(bL[0], bL[1], bfo + ob + j * 384 + 12288);
            #pragma unroll
            for (int i = 0; i < 4; i++) {
                mma_bf16(acc[i][j], aH[i], bH);
                mma_bf16(acc[i][j], aH[i], bL);
                mma_bf16(acc[i][j], aL[i], bH);
            }
        }
    }

    #pragma unroll
    for (int i = 0; i < 4; i++) {
        int gr0 = bm + m0w + i * 16 + trow;
        #pragma unroll
        for (int j = 0; j < 4; j++) {
            int gc = col0 + n0w + j * 8 + tq * 2;
            float2 v0 = make_float2(acc[i][j][0], acc[i][j][1]);
            float2 v1 = make_float2(acc[i][j][2], acc[i][j][3]);
            if (bias) {
                float b0 = bias[gc], b1 = bias[gc + 1];
                v0.x += b0; v0.y += b1;
                v1.x += b0; v1.y += b1;
            }
            if (relu) {
                v0.x = fmaxf(v0.x, 0.f); v0.y = fmaxf(v0.y, 0.f);
                v1.x = fmaxf(v1.x, 0.f); v1.y = fmaxf(v1.y, 0.f);
            }
            *(float2*)&out[(size_t)gr0 * HC + gc]       = v0;
            *(float2*)&out[(size_t)(gr0 + 8) * HC + gc] = v1;
        }
    }
}

// ---------------------------------------------------------------------------
// Fused GATv2 edge phase: WPN warps per node; each warp owns NV4*32 column
// quads starting at sub*NV4*32 (whole heads, since NV4*32 is a multiple of
// the per-head quad count 2^CSH). Online softmax per lane-owned head.
// ---------------------------------------------------------------------------
template <int NV4, int CSH, int WPN>
__global__ void gat_edge_fused(const float4* __restrict__ xl4,
                               const float4* __restrict__ xr4,
                               const float4* __restrict__ att4,
                               const int* __restrict__ ptr,
                               const int* __restrict__ csrc,
                               float4* __restrict__ out4, int Nn, int HC4) {
    int gw   = (blockIdx.x * blockDim.x + threadIdx.x) >> 5;
    int lane = threadIdx.x & 31;
    int n    = gw / WPN;
    int sub  = gw - n * WPN;
    if (n >= Nn) return;
    const int cb = sub * NV4 * 32;   // column-quad base for this warp

    float4 xr[NV4], at[NV4];
    #pragma unroll
    for (int r = 0; r < NV4; r++) {
        xr[r] = xr4[(size_t)n * HC4 + cb + r * 32 + lane];
        at[r] = att4[cb + r * 32 + lane];
    }

    float m[NV4], z[NV4];
    float4 acc[NV4];
    #pragma unroll
    for (int r = 0; r < NV4; r++) {
        m[r] = -1e30f; z[r] = 0.f;
        acc[r] = make_float4(0.f, 0.f, 0.f, 0.f);
    }

    int beg = ptr[n], end = ptr[n + 1];
    if (beg >= end) return;

    float4 xv[NV4];
    {
        int s = csrc[beg];
        #pragma unroll
        for (int r = 0; r < NV4; r++)
            xv[r] = xl4[(size_t)s * HC4 + cb + r * 32 + lane];
    }

    for (int i = beg; i < end; i++) {
        float4 xn[NV4];
        bool more = (i + 1 < end);
        if (more) {
            int s2 = csrc[i + 1];
            #pragma unroll
            for (int r = 0; r < NV4; r++)
                xn[r] = xl4[(size_t)s2 * HC4 + cb + r * 32 + lane];
        }

        float p[NV4];
        #pragma unroll
        for (int r = 0; r < NV4; r++) {
            float v, s = 0.f;
            v = xv[r].x + xr[r].x; v = (v > 0.f) ? v : 0.2f * v; s += at[r].x * v;
            v = xv[r].y + xr[r].y; v = (v > 0.f) ? v : 0.2f * v; s += at[r].y * v;
            v = xv[r].z + xr[r].z; v = (v > 0.f) ? v : 0.2f * v; s += at[r].z * v;
            v = xv[r].w + xr[r].w; v = (v > 0.f) ? v : 0.2f * v; s += at[r].w * v;
            p[r] = s;
        }
        #pragma unroll
        for (int r = 0; r < NV4; r++) {
            #pragma unroll
            for (int off = (1 << CSH) >> 1; off > 0; off >>= 1)
                p[r] += __shfl_xor_sync(0xffffffffu, p[r], off);
        }
        #pragma unroll
        for (int r = 0; r < NV4; r++) {
            float mn = fmaxf(m[r], p[r]);
            float sc = expf(m[r] - mn);
            float pe = expf(p[r] - mn);
            z[r] = z[r] * sc + pe;
            m[r] = mn;
            acc[r].x = acc[r].x * sc + pe * xv[r].x;
            acc[r].y = acc[r].y * sc + pe * xv[r].y;
            acc[r].z = acc[r].z * sc + pe * xv[r].z;
            acc[r].w = acc[r].w * sc + pe * xv[r].w;
        }
        if (more) {
            #pragma unroll
            for (int r = 0; r < NV4; r++) xv[r] = xn[r];
        }
    }

    #pragma unroll
    for (int r = 0; r < NV4; r++) {
        float inv = 1.f / (z[r] + 1e-16f);
        float4 o;
        o.x = acc[r].x * inv; o.y = acc[r].y * inv;
        o.z = acc[r].z * inv; o.w = acc[r].w * inv;
        out4[(size_t)n * HC4 + cb + r * 32 + lane] = o;
    }
}

// ---------------------------------------------------------------------------
// GraphNorm
// ---------------------------------------------------------------------------
__global__ void colstats_kernel(const float4* __restrict__ x4, float* __restrict__ stats,
                                int Nn, int Cn4, int lg) {
    int r0   = blockIdx.x * 64;
    int rend = min(r0 + 64, Nn);
    int tx  = threadIdx.x & (Cn4 - 1);
    int ty  = threadIdx.x >> lg;
    int nty = 256 >> lg;
    float4 s = make_float4(0.f, 0.f, 0.f, 0.f);
    float4 q = make_float4(0.f, 0.f, 0.f, 0.f);
    for (int r = r0 + ty; r < rend; r += nty) {
        float4 v = x4[(size_t)r * Cn4 + tx];
        s.x += v.x; s.y += v.y; s.z += v.z; s.w += v.w;
        q.x += v.x * v.x; q.y += v.y * v.y; q.z += v.z * v.z; q.w += v.w * v.w;
    }
    int Cn = Cn4 * 4;
    int c = tx * 4;
    atomicAdd(&stats[c + 0], s.x); atomicAdd(&stats[c + 1], s.y);
    atomicAdd(&stats[c + 2], s.z); atomicAdd(&stats[c + 3], s.w);
    atomicAdd(&stats[Cn + c + 0], q.x); atomicAdd(&stats[Cn + c + 1], q.y);
    atomicAdd(&stats[Cn + c + 2], q.z); atomicAdd(&stats[Cn + c + 3], q.w);
}

__global__ void colscale_kernel(const float* __restrict__ stats,
                                const float* __restrict__ bias,
                                const float* __restrict__ gw, const float* __restrict__ gb,
                                const float* __restrict__ gm,
                                float* __restrict__ colA, float* __restrict__ colS,
                                int Nn, int Cn) {
    int c = blockIdx.x * blockDim.x + threadIdx.x;
    if (c >= Cn) return;
    float invN = 1.0f / (float)Nn;
    float ma = stats[c] * invN;
    float q  = stats[Cn + c] * invN;
    float b  = bias[c];
    float mx = ma + b;
    float tt = b - gm[c] * mx;
    float var = q + 2.f * tt * ma + tt * tt;
    var = fmaxf(var, 0.f);
    float A = gw[c] * rsqrtf(var + 1e-5f);
    colA[c] = A;
    colS[c] = A * tt + gb[c];
}

__global__ void norm_relu_split_kernel(float4* __restrict__ x4,
                                       const float4* __restrict__ colA4,
                                       const float4* __restrict__ colS4,
                                       uint32_t* __restrict__ xph,
                                       uint32_t* __restrict__ xpl,
                                       int total4, int Cn4, int wb) {
    int i = blockIdx.x * blockDim.x + threadIdx.x;
    if (i >= total4) return;
    int c = i % Cn4;
    float4 v = x4[i];
    float4 A = colA4[c];
    float4 S = colS4[c];
    v.x = fmaxf(A.x * v.x + S.x, 0.f);
    v.y = fmaxf(A.y * v.y + S.y, 0.f);
    v.z = fmaxf(A.z * v.z + S.z, 0.f);
    v.w = fmaxf(A.w * v.w + S.w, 0.f);
    if (wb) x4[i] = v;
    uint32_t h0, l0, h1, l1;
    packsplit(v.x, v.y, h0, l0);
    packsplit(v.z, v.w, h1, l1);
    xph[2 * i]     = h0; xph[2 * i + 1] = h1;
    xpl[2 * i]     = l0; xpl[2 * i + 1] = l1;
}

// ---------------------------------------------------------------------------
// Pooling
// ---------------------------------------------------------------------------
__global__ void gate_kernel(const float4* __restrict__ hidden4, const float4* __restrict__ aW24,
                            const float* __restrict__ ab2, float* __restrict__ gate, int Nn) {
    int gw   = (blockIdx.x * blockDim.x + threadIdx.x) >> 5;
    int lane = threadIdx.x & 31;
    if (gw >= Nn) return;
    float4 h = hidden4[(size_t)gw * 32 + lane];
    float4 w = aW24[lane];
    float acc = h.x * w.x + h.y * w.y + h.z * w.z + h.w * w.w;
    #pragma unroll
    for (int o = 16; o > 0; o >>= 1) acc += __shfl_down_sync(0xffffffffu, acc, o);
    if (lane == 0) gate[gw] = acc + ab2[0];
}

__device__ __forceinline__ int lower_bound_dev(const int* __restrict__ a, int n, int v) {
    int lo = 0, hi = n;
    while (lo < hi) {
        int mid = (lo + hi) >> 1;
        if (a[mid] < v) lo = mid + 1; else hi = mid;
    }
    return lo;
}

__global__ void pool_kernel(const float* __restrict__ x, const float* __restrict__ gate,
                            const int* __restrict__ batch, float* __restrict__ out, int Nn) {
    __shared__ float red[128];
    __shared__ float wbuf[128];
    int b = blockIdx.x;
    int t = threadIdx.x;
    int beg = lower_bound_dev(batch, Nn, b);
    int end = lower_bound_dev(batch, Nn, b + 1);

    float mx = -1e30f;
    for (int n = beg + t; n < end; n += 128) mx = fmaxf(mx, gate[n]);
    red[t] = mx; __syncthreads();
    for (int o = 64; o > 0; o >>= 1) {
        if (t < o) red[t] = fmaxf(red[t], red[t + o]);
        __syncthreads();
    }
    float m = red[0];
    if (m < -1e29f) m = 0.f;
    __syncthreads();

    float zs = 0.f;
    for (int n = beg + t; n < end; n += 128) zs += expf(gate[n] - m);
    red[t] = zs; __syncthreads();
    for (int o = 64; o > 0; o >>= 1) {
        if (t < o) red[t] += red[t + o];
        __syncthreads();
    }
    float inv = 1.f / (red[0] + 1e-16f);
    __syncthreads();

    float acc = 0.f;
    for (int base = beg; base < end; base += 128) {
        int n = base + t;
        wbuf[t] = (n < end) ? expf(gate[n] - m) * inv : 0.f;
        __syncthreads();
        int cnt = min(128, end - base);
        for (int k = 0; k < cnt; k++)
            acc += wbuf[k] * x[(size_t)(base + k) * 128 + t];
        __syncthreads();
    }
    out[b * 128 + t] = acc;
}

// ---------------------------------------------------------------------------
// Host orchestration
// ---------------------------------------------------------------------------
extern "C" void kernel_launch(void* const* d_in, const int* in_sizes, int n_in,
                              void* d_out, int out_size) {
    const float* x0    = (const float*)d_in[0];
    const int*   ei    = (const int*)d_in[1];
    const int*   batch = (const int*)d_in[2];

    int N = in_sizes[0] / 960;
    int E = in_sizes[1] / 2;
    const int* src = ei;
    const int* dst = ei + E;
    int Et = E + N;

    float *p_xl, *p_xr, *p_a0, *p_a1, *p_stats, *p_colA, *p_colS, *p_hidden, *p_gate;
    uint32_t *p_xph, *p_xpl, *p_wph, *p_wpl;
    int *p_deg, *p_ptr, *p_pos, *p_csrc;
    cudaGetSymbolAddress((void**)&p_xl,    g_xl);
    cudaGetSymbolAddress((void**)&p_xr,    g_xr);
    cudaGetSymbolAddress((void**)&p_a0,    g_act0);
    cudaGetSymbolAddress((void**)&p_a1,    g_act1);
    cudaGetSymbolAddress((void**)&p_stats, g_stats);
    cudaGetSymbolAddress((void**)&p_colA,  g_colA);
    cudaGetSymbolAddress((void**)&p_colS,  g_colS);
    cudaGetSymbolAddress((void**)&p_hidden,g_hidden);
    cudaGetSymbolAddress((void**)&p_gate,  g_gate);
    cudaGetSymbolAddress((void**)&p_xph,   g_xph);
    cudaGetSymbolAddress((void**)&p_xpl,   g_xpl);
    cudaGetSymbolAddress((void**)&p_wph,   g_wph);
    cudaGetSymbolAddress((void**)&p_wpl,   g_wpl);
    cudaGetSymbolAddress((void**)&p_deg,   g_deg);
    cudaGetSymbolAddress((void**)&p_ptr,   g_ptr);
    cudaGetSymbolAddress((void**)&p_pos,   g_pos);
    cudaGetSymbolAddress((void**)&p_csrc,  g_csrc);

    const int woffL[3] = {WOFF_L0L, WOFF_L1L, WOFF_L2L};
    const int woffR[3] = {WOFF_L0R, WOFF_L1R, WOFF_L2R};
    const int din[3] = {960, 512, 256};
    const int Cc[3]  = {128, 64, 32};

    // ---- Launches 1-3: layer-0 operand packs (so launch 4 = GEMM, profiled) ----
    {
        int K2 = 480, HC = 512, nel = K2 * HC;
        split_pack_B_kernel<<<(nel + 255) / 256, 256>>>(
            (const float*)d_in[3], p_wph + WOFF_L0L, p_wpl + WOFF_L0L, K2, HC);
        split_pack_B_kernel<<<(nel + 255) / 256, 256>>>(
            (const float*)d_in[4], p_wph + WOFF_L0R, p_wpl + WOFF_L0R, K2, HC);
    }
    split_pack_A_kernel<<<(N * 480 + 255) / 256, 256>>>(
        (const float2*)x0, p_xph, p_xpl, N * 480);

    // ---- Launch 4: layer-0 dual GEMM (ncu-profiled) ----
    {
        dim3 gblk(2 * 512 / 128, N / 128);
        bf16gemm_pre<<<gblk, 256>>>(p_xph, p_xpl,
                                    p_wph + WOFF_L0L, p_wpl + WOFF_L0L,
                                    p_wph + WOFF_L0R, p_wpl + WOFF_L0R,
                                    p_xl, p_xr, nullptr, 0, N, 480, 512);
    }

    // ---- CSR build ----
    fill_i_kernel<<<(N + 255) / 256, 256>>>(p_deg, 0, N);
    csr_count_kernel<<<(Et + 255) / 256, 256>>>(dst, p_deg, E, N);
    csr_scan_kernel<<<1, 1024>>>(p_deg, p_ptr, p_pos, N);
    csr_scatter_kernel<<<(Et + 255) / 256, 256>>>(src, dst, p_pos, p_csrc, E, N);

    // ---- Remaining weight packs ----
    for (int l = 1; l < 3; l++) {
        int K2 = din[l] / 2, HC = HEADS * Cc[l];
        int nel = K2 * HC;
        split_pack_B_kernel<<<(nel + 255) / 256, 256>>>(
            (const float*)d_in[3 + 7 * l], p_wph + woffL[l], p_wpl + woffL[l], K2, HC);
        split_pack_B_kernel<<<(nel + 255) / 256, 256>>>(
            (const float*)d_in[4 + 7 * l], p_wph + woffR[l], p_wpl + woffR[l], K2, HC);
    }
    split_pack_B_kernel<<<(64 * 128 + 255) / 256, 256>>>(
        (const float*)d_in[24], p_wph + WOFF_AW1, p_wpl + WOFF_AW1, 64, 128);

    float* acts[3] = {p_a0, p_a1, p_a0};

    for (int l = 0; l < 3; l++) {
        int K2 = din[l] / 2;
        int C  = Cc[l];
        int HC = HEADS * C;
        int HC4 = HC / 4;
        int lg  = (HC4 == 128) ? 7 : (HC4 == 64 ? 6 : 5);
        const float* att = (const float*)d_in[5 + 7 * l];
        const float* bb  = (const float*)d_in[6 + 7 * l];
        const float* gw  = (const float*)d_in[7 + 7 * l];
        const float* gb  = (const float*)d_in[8 + 7 * l];
        const float* gm  = (const float*)d_in[9 + 7 * l];
        float* out = acts[l];

        if (l > 0) {
            dim3 gblk(2 * HC / 128, N / 128);
            bf16gemm_pre<<<gblk, 256>>>(p_xph, p_xpl,
                                        p_wph + woffL[l], p_wpl + woffL[l],
                                        p_wph + woffR[l], p_wpl + woffR[l],
                                        p_xl, p_xr, nullptr, 0, N, K2, HC);
        }

        // fused edge phase: WPN warps per node (heads split across warps)
        if (C == 128) {
            int eblocks = (N * 2 * 32 + 255) / 256;
            gat_edge_fused<2, 5, 2><<<eblocks, 256>>>(
                (const float4*)p_xl, (const float4*)p_xr, (const float4*)att,
                p_ptr, p_csrc, (float4*)out, N, HC4);
        } else if (C == 64) {
            int eblocks = (N * 2 * 32 + 255) / 256;
            gat_edge_fused<1, 4, 2><<<eblocks, 256>>>(
                (const float4*)p_xl, (const float4*)p_xr, (const float4*)att,
                p_ptr, p_csrc, (float4*)out, N, HC4);
        } else {
            int eblocks = (N * 32 + 255) / 256;
            gat_edge_fused<1, 3, 1><<<eblocks, 256>>>(
                (const float4*)p_xl, (const float4*)p_xr, (const float4*)att,
                p_ptr, p_csrc, (float4*)out, N, HC4);
        }

        fill_f_kernel<<<(2 * HC + 255) / 256, 256>>>(p_stats, 0.f, 2 * HC);
        colstats_kernel<<<(N + 63) / 64, 256>>>((const float4*)out, p_stats, N, HC4, lg);
        colscale_kernel<<<(HC + 255) / 256, 256>>>(p_stats, bb, gw, gb, gm,
                                                   p_colA, p_colS, N, HC);
        norm_relu_split_kernel<<<(N * HC4 + 255) / 256, 256>>>(
            (float4*)out, (const float4*)p_colA, (const float4*)p_colS,
            p_xph, p_xpl, N * HC4, HC4, (l == 2) ? 1 : 0);
    }

    // ---- Pooling ----
    const float* ab1 = (const float*)d_in[25];
    const float* aW2 = (const float*)d_in[26];
    const float* ab2 = (const float*)d_in[27];
    float* xfin = acts[2];

    dim3 hblk(1, N / 128);
    bf16gemm_pre<<<hblk, 256>>>(p_xph, p_xpl,
                                p_wph + WOFF_AW1, p_wpl + WOFF_AW1,
                                nullptr, nullptr,
                                p_hidden, nullptr, ab1, 1, N, 64, 128);
    gate_kernel<<<(N * 32 + 255) / 256, 256>>>((const float4*)p_hidden,
                                               (const float4*)aW2, ab2, p_gate, N);
    pool_kernel<<<NGRAPH, 128>>>(xfin, p_gate, batch, (float*)d_out, N);
}

// round 16
// speedup vs baseline: 1.1565x; 1.0333x over previous
#include <cuda_runtime.h>
#include <cuda_bf16.h>
#include <math.h>
#include <stdint.h>

// ---------------------------------------------------------------------------
// Problem constants
// ---------------------------------------------------------------------------
#define NMAX   16000
#define EMAX   256000
#define ETMAX  (EMAX + NMAX)
#define HEADS  4
#define MAXHC  512
#define NGRAPH 64
#define MAXK2  480

#define WOFF_L0L 0
#define WOFF_L0R 245760
#define WOFF_L1L 491520
#define WOFF_L1R 557056
#define WOFF_L2L 622592
#define WOFF_L2R 638976
#define WOFF_AW1 655360
#define WTOTAL   663552

// ---------------------------------------------------------------------------
// Static device scratch
// ---------------------------------------------------------------------------
__device__ float    g_xl   [NMAX * MAXHC];
__device__ float    g_xr   [NMAX * MAXHC];
__device__ float    g_act0 [NMAX * MAXHC];
__device__ float    g_act1 [NMAX * MAXHC];
__device__ float    g_stats[2 * MAXHC];
__device__ float    g_colA [MAXHC];
__device__ float    g_colS [MAXHC];
__device__ float    g_hidden[NMAX * 128];
__device__ float    g_gate [NMAX];
__device__ uint32_t g_xph  [NMAX * MAXK2];
__device__ uint32_t g_xpl  [NMAX * MAXK2];
__device__ uint32_t g_wph  [WTOTAL];
__device__ uint32_t g_wpl  [WTOTAL];
__device__ int      g_deg  [NMAX];
__device__ int      g_ptr  [NMAX + 1];
__device__ int      g_pos  [NMAX];
__device__ int      g_csrc [ETMAX];

// ---------------------------------------------------------------------------
// Helpers
// ---------------------------------------------------------------------------
__device__ __forceinline__ void packsplit(float x0, float x1,
                                          uint32_t& hi, uint32_t& lo) {
    __nv_bfloat16 h0 = __float2bfloat16_rn(x0);
    __nv_bfloat16 h1 = __float2bfloat16_rn(x1);
    float l0f = x0 - __bfloat162float(h0);
    float l1f = x1 - __bfloat162float(h1);
    __nv_bfloat16 l0 = __float2bfloat16_rn(l0f);
    __nv_bfloat16 l1 = __float2bfloat16_rn(l1f);
    __nv_bfloat162 hp = __halves2bfloat162(h0, h1);
    __nv_bfloat162 lp = __halves2bfloat162(l0, l1);
    hi = *reinterpret_cast<uint32_t*>(&hp);
    lo = *reinterpret_cast<uint32_t*>(&lp);
}

__global__ void fill_f_kernel(float* __restrict__ p, float v, int n) {
    int i = blockIdx.x * blockDim.x + threadIdx.x;
    if (i < n) p[i] = v;
}
__global__ void fill_i_kernel(int* __restrict__ p, int v, int n) {
    int i = blockIdx.x * blockDim.x + threadIdx.x;
    if (i < n) p[i] = v;
}

__global__ void split_pack_A_kernel(const float2* __restrict__ in,
                                    uint32_t* __restrict__ hi, uint32_t* __restrict__ lo,
                                    int n2) {
    int i = blockIdx.x * blockDim.x + threadIdx.x;
    if (i >= n2) return;
    float2 v = in[i];
    uint32_t h, l;
    packsplit(v.x, v.y, h, l);
    hi[i] = h; lo[i] = l;
}

// pack fp32 [K, HC] -> hi/lo uint32 in N-MAJOR layout [HC, K/2]
__global__ void split_pack_B_kernel(const float* __restrict__ W,
                                    uint32_t* __restrict__ hi, uint32_t* __restrict__ lo,
                                    int K2, int HC) {
    int i = blockIdx.x * blockDim.x + threadIdx.x;
    if (i >= K2 * HC) return;
    int n = i / K2, kp = i - n * K2;
    float x0 = W[(size_t)(2 * kp) * HC + n];
    float x1 = W[(size_t)(2 * kp + 1) * HC + n];
    uint32_t h, l;
    packsplit(x0, x1, h, l);
    hi[(size_t)n * K2 + kp] = h;
    lo[(size_t)n * K2 + kp] = l;
}

// ---------------------------------------------------------------------------
// CSR build over dst; stores gathered src per CSR slot.
// ---------------------------------------------------------------------------
__global__ void csr_count_kernel(const int* __restrict__ dst, int* __restrict__ deg,
                                 int E, int Nn) {
    int e = blockIdx.x * blockDim.x + threadIdx.x;
    int Et = E + Nn;
    if (e >= Et) return;
    int d = (e < E) ? dst[e] : (e - E);
    atomicAdd(&deg[d], 1);
}

__global__ void csr_scan_kernel(const int* __restrict__ deg, int* __restrict__ ptr,
                                int* __restrict__ pos, int n) {
    __shared__ int ss[1024];
    int t = threadIdx.x;
    int base = t * 16;
    int loc[16];
    int s = 0;
    #pragma unroll
    for (int i = 0; i < 16; i++) {
        int v = (base + i < n) ? deg[base + i] : 0;
        loc[i] = v; s += v;
    }
    ss[t] = s;
    __syncthreads();
    for (int off = 1; off < 1024; off <<= 1) {
        int v = (t >= off) ? ss[t - off] : 0;
        __syncthreads();
        ss[t] += v;
        __syncthreads();
    }
    int run = (t > 0) ? ss[t - 1] : 0;
    #pragma unroll
    for (int i = 0; i < 16; i++) {
        if (base + i < n) {
            ptr[base + i] = run;
            pos[base + i] = run;
            run += loc[i];
        }
    }
    if (t == 1023) ptr[n] = ss[1023];
}

__global__ void csr_scatter_kernel(const int* __restrict__ src, const int* __restrict__ dst,
                                   int* __restrict__ pos, int* __restrict__ csrc,
                                   int E, int Nn) {
    int e = blockIdx.x * blockDim.x + threadIdx.x;
    int Et = E + Nn;
    if (e >= Et) return;
    int d, s;
    if (e < E) { d = dst[e]; s = src[e]; } else { d = s = e - E; }
    int slot = atomicAdd(&pos[d], 1);
    csrc[slot] = s;
}

// ---------------------------------------------------------------------------
// bf16 3-term tensor-core GEMM (R10 version, verbatim): 2-stage cp.async +
// ldmatrix. A: hi/lo uint32 [M, K2]; B: hi/lo uint32 N-MAJOR [HC, K2].
// Block 128x128x(8 k-pairs), 8 warps (2x4), warp tile 64x32, mma m16n8k16.
// ---------------------------------------------------------------------------
__device__ __forceinline__ void mma_bf16(float* d, const uint32_t* a, const uint32_t* b) {
    asm volatile(
        "mma.sync.aligned.m16n8k16.row.col.f32.bf16.bf16.f32 "
        "{%0,%1,%2,%3}, {%4,%5,%6,%7}, {%8,%9}, {%0,%1,%2,%3};\n"
        : "+f"(d[0]), "+f"(d[1]), "+f"(d[2]), "+f"(d[3])
        : "r"(a[0]), "r"(a[1]), "r"(a[2]), "r"(a[3]), "r"(b[0]), "r"(b[1]));
}

#define LDSM4(r, a) asm volatile( \
    "ldmatrix.sync.aligned.m8n8.x4.shared.b16 {%0,%1,%2,%3}, [%4];" \
    : "=r"((r)[0]), "=r"((r)[1]), "=r"((r)[2]), "=r"((r)[3]) : "r"(a))
#define LDSM2(r0, r1, a) asm volatile( \
    "ldmatrix.sync.aligned.m8n8.x2.shared.b16 {%0,%1}, [%2];" \
    : "=r"(r0), "=r"(r1) : "r"(a))
#define CPA16(s, g) asm volatile( \
    "cp.async.cg.shared.global [%0], [%1], 16;" :: "r"(s), "l"(g))
#define CPCOMMIT() asm volatile("cp.async.commit_group;")
#define CPWAIT0()  asm volatile("cp.async.wait_group 0;")

__global__ void __launch_bounds__(256)
bf16gemm_pre(const uint32_t* __restrict__ XH, const uint32_t* __restrict__ XL,
             const uint32_t* __restrict__ WH0, const uint32_t* __restrict__ WL0,
             const uint32_t* __restrict__ WH1, const uint32_t* __restrict__ WL1,
             float* __restrict__ out0, float* __restrict__ out1,
             const float* __restrict__ bias, int relu,
             int M, int K2, int HC) {
    __shared__ uint32_t S[12288];
    uint32_t sbase = (uint32_t)__cvta_generic_to_shared(S);

    const int t  = threadIdx.x;
    const int bm = blockIdx.y * 128;
    int bn = blockIdx.x * 128;

    const uint32_t* WH = WH0;
    const uint32_t* WL = WL0;
    float* out = out0;
    int col0 = bn;
    if (WH1 != nullptr && bn >= HC) { WH = WH1; WL = WL1; out = out1; col0 = bn - HC; }

    const int lrow = t >> 1;
    const int lseg = t & 1;
    const uint32_t* ApH = XH + (size_t)(bm + lrow) * K2 + lseg * 4;
    const uint32_t* ApL = XL + (size_t)(bm + lrow) * K2 + lseg * 4;
    const uint32_t* BpH = WH + (size_t)(col0 + lrow) * K2 + lseg * 4;
    const uint32_t* BpL = WL + (size_t)(col0 + lrow) * K2 + lseg * 4;
    const uint32_t sst = sbase + (lrow * 12 + lseg * 4) * 4;

    const int wA   = t >> 5;
    const int lane = t & 31;
    const int m0w = (wA >> 2) * 64;
    const int n0w = (wA & 3) * 32;
    const int tq   = lane & 3;
    const int trow = lane >> 2;

    const uint32_t afo = sbase +
        ((m0w + (lane & 7) + ((lane >> 3) & 1) * 8) * 12 + ((lane >> 4) & 1) * 4) * 4;
    const uint32_t bfo = sbase + 24576 +
        ((n0w + (lane & 7)) * 12 + ((lane >> 3) & 1) * 4) * 4;

    float acc[4][4][4];
    #pragma unroll
    for (int i = 0; i < 4; i++)
        #pragma unroll
        for (int j = 0; j < 4; j++)
            #pragma unroll
            for (int r = 0; r < 4; r++) acc[i][j][r] = 0.f;

    CPA16(sst,          ApH);
    CPA16(sst + 12288,  ApL);
    CPA16(sst + 24576,  BpH);
    CPA16(sst + 36864,  BpL);
    CPCOMMIT();

    const int nt = K2 >> 3;
    for (int it = 0; it < nt; it++) {
        CPWAIT0();
        __syncthreads();
        if (it + 1 < nt) {
            int p0 = (it + 1) << 3;
            uint32_t o = ((it + 1) & 1) * 6144;
            CPA16(sst + o,          ApH + p0);
            CPA16(sst + o + 12288,  ApL + p0);
            CPA16(sst + o + 24576,  BpH + p0);
            CPA16(sst + o + 36864,  BpL + p0);
            CPCOMMIT();
        }

        uint32_t ob = (it & 1) * 6144;
        uint32_t aH[4][4], aL[4][4];
        #pragma unroll
        for (int i = 0; i < 4; i++) {
            LDSM4(aH[i], afo + ob + i * 768);
            LDSM4(aL[i], afo + ob + i * 768 + 12288);
        }
        #pragma unroll
        for (int j = 0; j < 4; j++) {
            uint32_t bH[2], bL[2];
            LDSM2(bH[0], bH[1], bfo + ob + j * 384);
            LDSM2(bL[0], bL[1], bfo + ob + j * 384 + 12288);
            #pragma unroll
            for (int i = 0; i < 4; i++) {
                mma_bf16(acc[i][j], aH[i], bH);
                mma_bf16(acc[i][j], aH[i], bL);
                mma_bf16(acc[i][j], aL[i], bH);
            }
        }
    }

    #pragma unroll
    for (int i = 0; i < 4; i++) {
        int gr0 = bm + m0w + i * 16 + trow;
        #pragma unroll
        for (int j = 0; j < 4; j++) {
            int gc = col0 + n0w + j * 8 + tq * 2;
            float2 v0 = make_float2(acc[i][j][0], acc[i][j][1]);
            float2 v1 = make_float2(acc[i][j][2], acc[i][j][3]);
            if (bias) {
                float b0 = bias[gc], b1 = bias[gc + 1];
                v0.x += b0; v0.y += b1;
                v1.x += b0; v1.y += b1;
            }
            if (relu) {
                v0.x = fmaxf(v0.x, 0.f); v0.y = fmaxf(v0.y, 0.f);
                v1.x = fmaxf(v1.x, 0.f); v1.y = fmaxf(v1.y, 0.f);
            }
            *(float2*)&out[(size_t)gr0 * HC + gc]       = v0;
            *(float2*)&out[(size_t)(gr0 + 8) * HC + gc] = v1;
        }
    }
}

// ---------------------------------------------------------------------------
// Fused GATv2 edge phase, warp per node, online softmax UNROLLED BY EDGE
// PAIRS: two independent load/logit/shuffle chains per iteration, merged
// into one state update (3 exp per pair instead of 4; same math).
// ---------------------------------------------------------------------------
template <int NV4, int CSH>
__global__ void gat_edge_fused(const float4* __restrict__ xl4,
                               const float4* __restrict__ xr4,
                               const float4* __restrict__ att4,
                               const int* __restrict__ ptr,
                               const int* __restrict__ csrc,
                               float4* __restrict__ out4, int Nn) {
    int n    = (blockIdx.x * blockDim.x + threadIdx.x) >> 5;
    int lane = threadIdx.x & 31;
    if (n >= Nn) return;
    const int HC4 = NV4 * 32;

    float4 xr[NV4], at[NV4];
    #pragma unroll
    for (int r = 0; r < NV4; r++) {
        xr[r] = xr4[(size_t)n * HC4 + r * 32 + lane];
        at[r] = att4[r * 32 + lane];
    }

    float m[NV4], z[NV4];
    float4 acc[NV4];
    #pragma unroll
    for (int r = 0; r < NV4; r++) {
        m[r] = -1e30f; z[r] = 0.f;
        acc[r] = make_float4(0.f, 0.f, 0.f, 0.f);
    }

    int beg = ptr[n], end = ptr[n + 1];

    int i = beg;
    // pairwise main loop
    for (; i + 1 < end; i += 2) {
        int s0 = csrc[i];
        int s1 = csrc[i + 1];
        float4 x0[NV4], x1[NV4];
        #pragma unroll
        for (int r = 0; r < NV4; r++) {
            x0[r] = xl4[(size_t)s0 * HC4 + r * 32 + lane];
            x1[r] = xl4[(size_t)s1 * HC4 + r * 32 + lane];
        }

        float p0[NV4], p1[NV4];
        #pragma unroll
        for (int r = 0; r < NV4; r++) {
            float v, sa = 0.f, sb = 0.f;
            v = x0[r].x + xr[r].x; v = (v > 0.f) ? v : 0.2f * v; sa += at[r].x * v;
            v = x0[r].y + xr[r].y; v = (v > 0.f) ? v : 0.2f * v; sa += at[r].y * v;
            v = x0[r].z + xr[r].z; v = (v > 0.f) ? v : 0.2f * v; sa += at[r].z * v;
            v = x0[r].w + xr[r].w; v = (v > 0.f) ? v : 0.2f * v; sa += at[r].w * v;
            v = x1[r].x + xr[r].x; v = (v > 0.f) ? v : 0.2f * v; sb += at[r].x * v;
            v = x1[r].y + xr[r].y; v = (v > 0.f) ? v : 0.2f * v; sb += at[r].y * v;
            v = x1[r].z + xr[r].z; v = (v > 0.f) ? v : 0.2f * v; sb += at[r].z * v;
            v = x1[r].w + xr[r].w; v = (v > 0.f) ? v : 0.2f * v; sb += at[r].w * v;
            p0[r] = sa; p1[r] = sb;
        }
        #pragma unroll
        for (int r = 0; r < NV4; r++) {
            #pragma unroll
            for (int off = (1 << CSH) >> 1; off > 0; off >>= 1) {
                p0[r] += __shfl_xor_sync(0xffffffffu, p0[r], off);
                p1[r] += __shfl_xor_sync(0xffffffffu, p1[r], off);
            }
        }
        #pragma unroll
        for (int r = 0; r < NV4; r++) {
            float mn = fmaxf(m[r], fmaxf(p0[r], p1[r]));
            float sc = expf(m[r] - mn);
            float e0 = expf(p0[r] - mn);
            float e1 = expf(p1[r] - mn);
            z[r] = z[r] * sc + e0 + e1;
            m[r] = mn;
            acc[r].x = acc[r].x * sc + e0 * x0[r].x + e1 * x1[r].x;
            acc[r].y = acc[r].y * sc + e0 * x0[r].y + e1 * x1[r].y;
            acc[r].z = acc[r].z * sc + e0 * x0[r].z + e1 * x1[r].z;
            acc[r].w = acc[r].w * sc + e0 * x0[r].w + e1 * x1[r].w;
        }
    }
    // odd tail
    if (i < end) {
        int s0 = csrc[i];
        float4 x0[NV4];
        #pragma unroll
        for (int r = 0; r < NV4; r++)
            x0[r] = xl4[(size_t)s0 * HC4 + r * 32 + lane];
        float p0[NV4];
        #pragma unroll
        for (int r = 0; r < NV4; r++) {
            float v, sa = 0.f;
            v = x0[r].x + xr[r].x; v = (v > 0.f) ? v : 0.2f * v; sa += at[r].x * v;
            v = x0[r].y + xr[r].y; v = (v > 0.f) ? v : 0.2f * v; sa += at[r].y * v;
            v = x0[r].z + xr[r].z; v = (v > 0.f) ? v : 0.2f * v; sa += at[r].z * v;
            v = x0[r].w + xr[r].w; v = (v > 0.f) ? v : 0.2f * v; sa += at[r].w * v;
            p0[r] = sa;
        }
        #pragma unroll
        for (int r = 0; r < NV4; r++) {
            #pragma unroll
            for (int off = (1 << CSH) >> 1; off > 0; off >>= 1)
                p0[r] += __shfl_xor_sync(0xffffffffu, p0[r], off);
        }
        #pragma unroll
        for (int r = 0; r < NV4; r++) {
            float mn = fmaxf(m[r], p0[r]);
            float sc = expf(m[r] - mn);
            float e0 = expf(p0[r] - mn);
            z[r] = z[r] * sc + e0;
            m[r] = mn;
            acc[r].x = acc[r].x * sc + e0 * x0[r].x;
            acc[r].y = acc[r].y * sc + e0 * x0[r].y;
            acc[r].z = acc[r].z * sc + e0 * x0[r].z;
            acc[r].w = acc[r].w * sc + e0 * x0[r].w;
        }
    }

    #pragma unroll
    for (int r = 0; r < NV4; r++) {
        float inv = 1.f / (z[r] + 1e-16f);
        float4 o;
        o.x = acc[r].x * inv; o.y = acc[r].y * inv;
        o.z = acc[r].z * inv; o.w = acc[r].w * inv;
        out4[(size_t)n * HC4 + r * 32 + lane] = o;
    }
}

// ---------------------------------------------------------------------------
// GraphNorm
// ---------------------------------------------------------------------------
__global__ void colstats_kernel(const float4* __restrict__ x4, float* __restrict__ stats,
                                int Nn, int Cn4, int lg) {
    int r0   = blockIdx.x * 64;
    int rend = min(r0 + 64, Nn);
    int tx  = threadIdx.x & (Cn4 - 1);
    int ty  = threadIdx.x >> lg;
    int nty = 256 >> lg;
    float4 s = make_float4(0.f, 0.f, 0.f, 0.f);
    float4 q = make_float4(0.f, 0.f, 0.f, 0.f);
    for (int r = r0 + ty; r < rend; r += nty) {
        float4 v = x4[(size_t)r * Cn4 + tx];
        s.x += v.x; s.y += v.y; s.z += v.z; s.w += v.w;
        q.x += v.x * v.x; q.y += v.y * v.y; q.z += v.z * v.z; q.w += v.w * v.w;
    }
    int Cn = Cn4 * 4;
    int c = tx * 4;
    atomicAdd(&stats[c + 0], s.x); atomicAdd(&stats[c + 1], s.y);
    atomicAdd(&stats[c + 2], s.z); atomicAdd(&stats[c + 3], s.w);
    atomicAdd(&stats[Cn + c + 0], q.x); atomicAdd(&stats[Cn + c + 1], q.y);
    atomicAdd(&stats[Cn + c + 2], q.z); atomicAdd(&stats[Cn + c + 3], q.w);
}

__global__ void colscale_kernel(const float* __restrict__ stats,
                                const float* __restrict__ bias,
                                const float* __restrict__ gw, const float* __restrict__ gb,
                                const float* __restrict__ gm,
                                float* __restrict__ colA, float* __restrict__ colS,
                                int Nn, int Cn) {
    int c = blockIdx.x * blockDim.x + threadIdx.x;
    if (c >= Cn) return;
    float invN = 1.0f / (float)Nn;
    float ma = stats[c] * invN;
    float q  = stats[Cn + c] * invN;
    float b  = bias[c];
    float mx = ma + b;
    float tt = b - gm[c] * mx;
    float var = q + 2.f * tt * ma + tt * tt;
    var = fmaxf(var, 0.f);
    float A = gw[c] * rsqrtf(var + 1e-5f);
    colA[c] = A;
    colS[c] = A * tt + gb[c];
}

__global__ void norm_relu_split_kernel(float4* __restrict__ x4,
                                       const float4* __restrict__ colA4,
                                       const float4* __restrict__ colS4,
                                       uint32_t* __restrict__ xph,
                                       uint32_t* __restrict__ xpl,
                                       int total4, int Cn4, int wb) {
    int i = blockIdx.x * blockDim.x + threadIdx.x;
    if (i >= total4) return;
    int c = i % Cn4;
    float4 v = x4[i];
    float4 A = colA4[c];
    float4 S = colS4[c];
    v.x = fmaxf(A.x * v.x + S.x, 0.f);
    v.y = fmaxf(A.y * v.y + S.y, 0.f);
    v.z = fmaxf(A.z * v.z + S.z, 0.f);
    v.w = fmaxf(A.w * v.w + S.w, 0.f);
    if (wb) x4[i] = v;
    uint32_t h0, l0, h1, l1;
    packsplit(v.x, v.y, h0, l0);
    packsplit(v.z, v.w, h1, l1);
    xph[2 * i]     = h0; xph[2 * i + 1] = h1;
    xpl[2 * i]     = l0; xpl[2 * i + 1] = l1;
}

// ---------------------------------------------------------------------------
// Pooling
// ---------------------------------------------------------------------------
__global__ void gate_kernel(const float4* __restrict__ hidden4, const float4* __restrict__ aW24,
                            const float* __restrict__ ab2, float* __restrict__ gate, int Nn) {
    int gw   = (blockIdx.x * blockDim.x + threadIdx.x) >> 5;
    int lane = threadIdx.x & 31;
    if (gw >= Nn) return;
    float4 h = hidden4[(size_t)gw * 32 + lane];
    float4 w = aW24[lane];
    float acc = h.x * w.x + h.y * w.y + h.z * w.z + h.w * w.w;
    #pragma unroll
    for (int o = 16; o > 0; o >>= 1) acc += __shfl_down_sync(0xffffffffu, acc, o);
    if (lane == 0) gate[gw] = acc + ab2[0];
}

__device__ __forceinline__ int lower_bound_dev(const int* __restrict__ a, int n, int v) {
    int lo = 0, hi = n;
    while (lo < hi) {
        int mid = (lo + hi) >> 1;
        if (a[mid] < v) lo = mid + 1; else hi = mid;
    }
    return lo;
}

__global__ void pool_kernel(const float* __restrict__ x, const float* __restrict__ gate,
                            const int* __restrict__ batch, float* __restrict__ out, int Nn) {
    __shared__ float red[128];
    __shared__ float wbuf[128];
    int b = blockIdx.x;
    int t = threadIdx.x;
    int beg = lower_bound_dev(batch, Nn, b);
    int end = lower_bound_dev(batch, Nn, b + 1);

    float mx = -1e30f;
    for (int n = beg + t; n < end; n += 128) mx = fmaxf(mx, gate[n]);
    red[t] = mx; __syncthreads();
    for (int o = 64; o > 0; o >>= 1) {
        if (t < o) red[t] = fmaxf(red[t], red[t + o]);
        __syncthreads();
    }
    float m = red[0];
    if (m < -1e29f) m = 0.f;
    __syncthreads();

    float zs = 0.f;
    for (int n = beg + t; n < end; n += 128) zs += expf(gate[n] - m);
    red[t] = zs; __syncthreads();
    for (int o = 64; o > 0; o >>= 1) {
        if (t < o) red[t] += red[t + o];
        __syncthreads();
    }
    float inv = 1.f / (red[0] + 1e-16f);
    __syncthreads();

    float acc = 0.f;
    for (int base = beg; base < end; base += 128) {
        int n = base + t;
        wbuf[t] = (n < end) ? expf(gate[n] - m) * inv : 0.f;
        __syncthreads();
        int cnt = min(128, end - base);
        for (int k = 0; k < cnt; k++)
            acc += wbuf[k] * x[(size_t)(base + k) * 128 + t];
        __syncthreads();
    }
    out[b * 128 + t] = acc;
}

// ---------------------------------------------------------------------------
// Host orchestration
// ---------------------------------------------------------------------------
extern "C" void kernel_launch(void* const* d_in, const int* in_sizes, int n_in,
                              void* d_out, int out_size) {
    const float* x0    = (const float*)d_in[0];
    const int*   ei    = (const int*)d_in[1];
    const int*   batch = (const int*)d_in[2];

    int N = in_sizes[0] / 960;
    int E = in_sizes[1] / 2;
    const int* src = ei;
    const int* dst = ei + E;
    int Et = E + N;

    float *p_xl, *p_xr, *p_a0, *p_a1, *p_stats, *p_colA, *p_colS, *p_hidden, *p_gate;
    uint32_t *p_xph, *p_xpl, *p_wph, *p_wpl;
    int *p_deg, *p_ptr, *p_pos, *p_csrc;
    cudaGetSymbolAddress((void**)&p_xl,    g_xl);
    cudaGetSymbolAddress((void**)&p_xr,    g_xr);
    cudaGetSymbolAddress((void**)&p_a0,    g_act0);
    cudaGetSymbolAddress((void**)&p_a1,    g_act1);
    cudaGetSymbolAddress((void**)&p_stats, g_stats);
    cudaGetSymbolAddress((void**)&p_colA,  g_colA);
    cudaGetSymbolAddress((void**)&p_colS,  g_colS);
    cudaGetSymbolAddress((void**)&p_hidden,g_hidden);
    cudaGetSymbolAddress((void**)&p_gate,  g_gate);
    cudaGetSymbolAddress((void**)&p_xph,   g_xph);
    cudaGetSymbolAddress((void**)&p_xpl,   g_xpl);
    cudaGetSymbolAddress((void**)&p_wph,   g_wph);
    cudaGetSymbolAddress((void**)&p_wpl,   g_wpl);
    cudaGetSymbolAddress((void**)&p_deg,   g_deg);
    cudaGetSymbolAddress((void**)&p_ptr,   g_ptr);
    cudaGetSymbolAddress((void**)&p_pos,   g_pos);
    cudaGetSymbolAddress((void**)&p_csrc,  g_csrc);

    const int woffL[3] = {WOFF_L0L, WOFF_L1L, WOFF_L2L};
    const int woffR[3] = {WOFF_L0R, WOFF_L1R, WOFF_L2R};
    const int din[3] = {960, 512, 256};
    const int Cc[3]  = {128, 64, 32};

    // ---- Launches 1-3: layer-0 operand packs (so launch 4 = GEMM, profiled) ----
    {
        int K2 = 480, HC = 512, nel = K2 * HC;
        split_pack_B_kernel<<<(nel + 255) / 256, 256>>>(
            (const float*)d_in[3], p_wph + WOFF_L0L, p_wpl + WOFF_L0L, K2, HC);
        split_pack_B_kernel<<<(nel + 255) / 256, 256>>>(
            (const float*)d_in[4], p_wph + WOFF_L0R, p_wpl + WOFF_L0R, K2, HC);
    }
    split_pack_A_kernel<<<(N * 480 + 255) / 256, 256>>>(
        (const float2*)x0, p_xph, p_xpl, N * 480);

    // ---- Launch 4: layer-0 dual GEMM (ncu-profiled) ----
    {
        dim3 gblk(2 * 512 / 128, N / 128);
        bf16gemm_pre<<<gblk, 256>>>(p_xph, p_xpl,
                                    p_wph + WOFF_L0L, p_wpl + WOFF_L0L,
                                    p_wph + WOFF_L0R, p_wpl + WOFF_L0R,
                                    p_xl, p_xr, nullptr, 0, N, 480, 512);
    }

    // ---- CSR build ----
    fill_i_kernel<<<(N + 255) / 256, 256>>>(p_deg, 0, N);
    csr_count_kernel<<<(Et + 255) / 256, 256>>>(dst, p_deg, E, N);
    csr_scan_kernel<<<1, 1024>>>(p_deg, p_ptr, p_pos, N);
    csr_scatter_kernel<<<(Et + 255) / 256, 256>>>(src, dst, p_pos, p_csrc, E, N);

    // ---- Remaining weight packs ----
    for (int l = 1; l < 3; l++) {
        int K2 = din[l] / 2, HC = HEADS * Cc[l];
        int nel = K2 * HC;
        split_pack_B_kernel<<<(nel + 255) / 256, 256>>>(
            (const float*)d_in[3 + 7 * l], p_wph + woffL[l], p_wpl + woffL[l], K2, HC);
        split_pack_B_kernel<<<(nel + 255) / 256, 256>>>(
            (const float*)d_in[4 + 7 * l], p_wph + woffR[l], p_wpl + woffR[l], K2, HC);
    }
    split_pack_B_kernel<<<(64 * 128 + 255) / 256, 256>>>(
        (const float*)d_in[24], p_wph + WOFF_AW1, p_wpl + WOFF_AW1, 64, 128);

    float* acts[3] = {p_a0, p_a1, p_a0};

    for (int l = 0; l < 3; l++) {
        int K2 = din[l] / 2;
        int C  = Cc[l];
        int HC = HEADS * C;
        int HC4 = HC / 4;
        int lg  = (HC4 == 128) ? 7 : (HC4 == 64 ? 6 : 5);
        const float* att = (const float*)d_in[5 + 7 * l];
        const float* bb  = (const float*)d_in[6 + 7 * l];
        const float* gw  = (const float*)d_in[7 + 7 * l];
        const float* gb  = (const float*)d_in[8 + 7 * l];
        const float* gm  = (const float*)d_in[9 + 7 * l];
        float* out = acts[l];

        if (l > 0) {
            dim3 gblk(2 * HC / 128, N / 128);
            bf16gemm_pre<<<gblk, 256>>>(p_xph, p_xpl,
                                        p_wph + woffL[l], p_wpl + woffL[l],
                                        p_wph + woffR[l], p_wpl + woffR[l],
                                        p_xl, p_xr, nullptr, 0, N, K2, HC);
        }

        int eblocks = (N * 32 + 255) / 256;
        if (C == 128)
            gat_edge_fused<4, 5><<<eblocks, 256>>>(
                (const float4*)p_xl, (const float4*)p_xr, (const float4*)att,
                p_ptr, p_csrc, (float4*)out, N);
        else if (C == 64)
            gat_edge_fused<2, 4><<<eblocks, 256>>>(
                (const float4*)p_xl, (const float4*)p_xr, (const float4*)att,
                p_ptr, p_csrc, (float4*)out, N);
        else
            gat_edge_fused<1, 3><<<eblocks, 256>>>(
                (const float4*)p_xl, (const float4*)p_xr, (const float4*)att,
                p_ptr, p_csrc, (float4*)out, N);

        fill_f_kernel<<<(2 * HC + 255) / 256, 256>>>(p_stats, 0.f, 2 * HC);
        colstats_kernel<<<(N + 63) / 64, 256>>>((const float4*)out, p_stats, N, HC4, lg);
        colscale_kernel<<<(HC + 255) / 256, 256>>>(p_stats, bb, gw, gb, gm,
                                                   p_colA, p_colS, N, HC);
        norm_relu_split_kernel<<<(N * HC4 + 255) / 256, 256>>>(
            (float4*)out, (const float4*)p_colA, (const float4*)p_colS,
            p_xph, p_xpl, N * HC4, HC4, (l == 2) ? 1 : 0);
    }

    // ---- Pooling ----
    const float* ab1 = (const float*)d_in[25];
    const float* aW2 = (const float*)d_in[26];
    const float* ab2 = (const float*)d_in[27];
    float* xfin = acts[2];

    dim3 hblk(1, N / 128);
    bf16gemm_pre<<<hblk, 256>>>(p_xph, p_xpl,
                                p_wph + WOFF_AW1, p_wpl + WOFF_AW1,
                                nullptr, nullptr,
                                p_hidden, nullptr, ab1, 1, N, 64, 128);
    gate_kernel<<<(N * 32 + 255) / 256, 256>>>((const float4*)p_hidden,
                                               (const float4*)aW2, ab2, p_gate, N);
    pool_kernel<<<NGRAPH, 128>>>(xfin, p_gate, batch, (float*)d_out, N);
}

// round 17
// speedup vs baseline: 1.3303x; 1.1503x over previous
#include <cuda_runtime.h>
#include <cuda_bf16.h>
#include <math.h>
#include <stdint.h>

// ---------------------------------------------------------------------------
// Problem constants
// ---------------------------------------------------------------------------
#define NMAX   16000
#define EMAX   256000
#define ETMAX  (EMAX + NMAX)
#define HEADS  4
#define MAXHC  512
#define NGRAPH 64
#define MAXK2  480

#define WOFF_L0L 0
#define WOFF_L0R 245760
#define WOFF_L1L 491520
#define WOFF_L1R 557056
#define WOFF_L2L 622592
#define WOFF_L2R 638976
#define WOFF_AW1 655360
#define WTOTAL   663552

// ---------------------------------------------------------------------------
// Static device scratch
// ---------------------------------------------------------------------------
__device__ float    g_xl   [NMAX * MAXHC];
__device__ float    g_xr   [NMAX * MAXHC];
__device__ float    g_act0 [NMAX * MAXHC];
__device__ float    g_act1 [NMAX * MAXHC];
__device__ float    g_stats[2 * MAXHC];
__device__ float    g_colA [MAXHC];
__device__ float    g_colS [MAXHC];
__device__ float    g_hidden[NMAX * 128];
__device__ float    g_gate [NMAX];
__device__ uint32_t g_xph  [NMAX * MAXK2];
__device__ uint32_t g_xpl  [NMAX * MAXK2];
__device__ uint32_t g_wph  [WTOTAL];
__device__ uint32_t g_wpl  [WTOTAL];
__device__ int      g_deg  [NMAX];
__device__ int      g_ptr  [NMAX + 1];
__device__ int      g_pos  [NMAX];
__device__ int      g_csrc [ETMAX];

// ---------------------------------------------------------------------------
// Helpers
// ---------------------------------------------------------------------------
__device__ __forceinline__ void packsplit(float x0, float x1,
                                          uint32_t& hi, uint32_t& lo) {
    __nv_bfloat16 h0 = __float2bfloat16_rn(x0);
    __nv_bfloat16 h1 = __float2bfloat16_rn(x1);
    float l0f = x0 - __bfloat162float(h0);
    float l1f = x1 - __bfloat162float(h1);
    __nv_bfloat16 l0 = __float2bfloat16_rn(l0f);
    __nv_bfloat16 l1 = __float2bfloat16_rn(l1f);
    __nv_bfloat162 hp = __halves2bfloat162(h0, h1);
    __nv_bfloat162 lp = __halves2bfloat162(l0, l1);
    hi = *reinterpret_cast<uint32_t*>(&hp);
    lo = *reinterpret_cast<uint32_t*>(&lp);
}

__global__ void fill_f_kernel(float* __restrict__ p, float v, int n) {
    int i = blockIdx.x * blockDim.x + threadIdx.x;
    if (i < n) p[i] = v;
}
__global__ void fill_i_kernel(int* __restrict__ p, int v, int n) {
    int i = blockIdx.x * blockDim.x + threadIdx.x;
    if (i < n) p[i] = v;
}

__global__ void split_pack_A_kernel(const float2* __restrict__ in,
                                    uint32_t* __restrict__ hi, uint32_t* __restrict__ lo,
                                    int n2) {
    int i = blockIdx.x * blockDim.x + threadIdx.x;
    if (i >= n2) return;
    float2 v = in[i];
    uint32_t h, l;
    packsplit(v.x, v.y, h, l);
    hi[i] = h; lo[i] = l;
}

// pack fp32 [K, HC] -> hi/lo uint32 in N-MAJOR layout [HC, K/2]
__global__ void split_pack_B_kernel(const float* __restrict__ W,
                                    uint32_t* __restrict__ hi, uint32_t* __restrict__ lo,
                                    int K2, int HC) {
    int i = blockIdx.x * blockDim.x + threadIdx.x;
    if (i >= K2 * HC) return;
    int n = i / K2, kp = i - n * K2;
    float x0 = W[(size_t)(2 * kp) * HC + n];
    float x1 = W[(size_t)(2 * kp + 1) * HC + n];
    uint32_t h, l;
    packsplit(x0, x1, h, l);
    hi[(size_t)n * K2 + kp] = h;
    lo[(size_t)n * K2 + kp] = l;
}

// ---------------------------------------------------------------------------
// CSR build over dst; stores gathered src per CSR slot.
// ---------------------------------------------------------------------------
__global__ void csr_count_kernel(const int* __restrict__ dst, int* __restrict__ deg,
                                 int E, int Nn) {
    int e = blockIdx.x * blockDim.x + threadIdx.x;
    int Et = E + Nn;
    if (e >= Et) return;
    int d = (e < E) ? dst[e] : (e - E);
    atomicAdd(&deg[d], 1);
}

__global__ void csr_scan_kernel(const int* __restrict__ deg, int* __restrict__ ptr,
                                int* __restrict__ pos, int n) {
    __shared__ int ss[1024];
    int t = threadIdx.x;
    int base = t * 16;
    int loc[16];
    int s = 0;
    #pragma unroll
    for (int i = 0; i < 16; i++) {
        int v = (base + i < n) ? deg[base + i] : 0;
        loc[i] = v; s += v;
    }
    ss[t] = s;
    __syncthreads();
    for (int off = 1; off < 1024; off <<= 1) {
        int v = (t >= off) ? ss[t - off] : 0;
        __syncthreads();
        ss[t] += v;
        __syncthreads();
    }
    int run = (t > 0) ? ss[t - 1] : 0;
    #pragma unroll
    for (int i = 0; i < 16; i++) {
        if (base + i < n) {
            ptr[base + i] = run;
            pos[base + i] = run;
            run += loc[i];
        }
    }
    if (t == 1023) ptr[n] = ss[1023];
}

__global__ void csr_scatter_kernel(const int* __restrict__ src, const int* __restrict__ dst,
                                   int* __restrict__ pos, int* __restrict__ csrc,
                                   int E, int Nn) {
    int e = blockIdx.x * blockDim.x + threadIdx.x;
    int Et = E + Nn;
    if (e >= Et) return;
    int d, s;
    if (e < E) { d = dst[e]; s = src[e]; } else { d = s = e - E; }
    int slot = atomicAdd(&pos[d], 1);
    csrc[slot] = s;
}

// ---------------------------------------------------------------------------
// bf16 3-term tensor-core GEMM (R10 version, verbatim).
// ---------------------------------------------------------------------------
__device__ __forceinline__ void mma_bf16(float* d, const uint32_t* a, const uint32_t* b) {
    asm volatile(
        "mma.sync.aligned.m16n8k16.row.col.f32.bf16.bf16.f32 "
        "{%0,%1,%2,%3}, {%4,%5,%6,%7}, {%8,%9}, {%0,%1,%2,%3};\n"
        : "+f"(d[0]), "+f"(d[1]), "+f"(d[2]), "+f"(d[3])
        : "r"(a[0]), "r"(a[1]), "r"(a[2]), "r"(a[3]), "r"(b[0]), "r"(b[1]));
}

#define LDSM4(r, a) asm volatile( \
    "ldmatrix.sync.aligned.m8n8.x4.shared.b16 {%0,%1,%2,%3}, [%4];" \
    : "=r"((r)[0]), "=r"((r)[1]), "=r"((r)[2]), "=r"((r)[3]) : "r"(a))
#define LDSM2(r0, r1, a) asm volatile( \
    "ldmatrix.sync.aligned.m8n8.x2.shared.b16 {%0,%1}, [%2];" \
    : "=r"(r0), "=r"(r1) : "r"(a))
#define CPA16(s, g) asm volatile( \
    "cp.async.cg.shared.global [%0], [%1], 16;" :: "r"(s), "l"(g))
#define CPCOMMIT() asm volatile("cp.async.commit_group;")
#define CPWAIT0()  asm volatile("cp.async.wait_group 0;")

__global__ void __launch_bounds__(256)
bf16gemm_pre(const uint32_t* __restrict__ XH, const uint32_t* __restrict__ XL,
             const uint32_t* __restrict__ WH0, const uint32_t* __restrict__ WL0,
             const uint32_t* __restrict__ WH1, const uint32_t* __restrict__ WL1,
             float* __restrict__ out0, float* __restrict__ out1,
             const float* __restrict__ bias, int relu,
             int M, int K2, int HC) {
    __shared__ uint32_t S[12288];
    uint32_t sbase = (uint32_t)__cvta_generic_to_shared(S);

    const int t  = threadIdx.x;
    const int bm = blockIdx.y * 128;
    int bn = blockIdx.x * 128;

    const uint32_t* WH = WH0;
    const uint32_t* WL = WL0;
    float* out = out0;
    int col0 = bn;
    if (WH1 != nullptr && bn >= HC) { WH = WH1; WL = WL1; out = out1; col0 = bn - HC; }

    const int lrow = t >> 1;
    const int lseg = t & 1;
    const uint32_t* ApH = XH + (size_t)(bm + lrow) * K2 + lseg * 4;
    const uint32_t* ApL = XL + (size_t)(bm + lrow) * K2 + lseg * 4;
    const uint32_t* BpH = WH + (size_t)(col0 + lrow) * K2 + lseg * 4;
    const uint32_t* BpL = WL + (size_t)(col0 + lrow) * K2 + lseg * 4;
    const uint32_t sst = sbase + (lrow * 12 + lseg * 4) * 4;

    const int wA   = t >> 5;
    const int lane = t & 31;
    const int m0w = (wA >> 2) * 64;
    const int n0w = (wA & 3) * 32;
    const int tq   = lane & 3;
    const int trow = lane >> 2;

    const uint32_t afo = sbase +
        ((m0w + (lane & 7) + ((lane >> 3) & 1) * 8) * 12 + ((lane >> 4) & 1) * 4) * 4;
    const uint32_t bfo = sbase + 24576 +
        ((n0w + (lane & 7)) * 12 + ((lane >> 3) & 1) * 4) * 4;

    float acc[4][4][4];
    #pragma unroll
    for (int i = 0; i < 4; i++)
        #pragma unroll
        for (int j = 0; j < 4; j++)
            #pragma unroll
            for (int r = 0; r < 4; r++) acc[i][j][r] = 0.f;

    CPA16(sst,          ApH);
    CPA16(sst + 12288,  ApL);
    CPA16(sst + 24576,  BpH);
    CPA16(sst + 36864,  BpL);
    CPCOMMIT();

    const int nt = K2 >> 3;
    for (int it = 0; it < nt; it++) {
        CPWAIT0();
        __syncthreads();
        if (it + 1 < nt) {
            int p0 = (it + 1) << 3;
            uint32_t o = ((it + 1) & 1) * 6144;
            CPA16(sst + o,          ApH + p0);
            CPA16(sst + o + 12288,  ApL + p0);
            CPA16(sst + o + 24576,  BpH + p0);
            CPA16(sst + o + 36864,  BpL + p0);
            CPCOMMIT();
        }

        uint32_t ob = (it & 1) * 6144;
        uint32_t aH[4][4], aL[4][4];
        #pragma unroll
        for (int i = 0; i < 4; i++) {
            LDSM4(aH[i], afo + ob + i * 768);
            LDSM4(aL[i], afo + ob + i * 768 + 12288);
        }
        #pragma unroll
        for (int j = 0; j < 4; j++) {
            uint32_t bH[2], bL[2];
            LDSM2(bH[0], bH[1], bfo + ob + j * 384);
            LDSM2(bL[0], bL[1], bfo + ob + j * 384 + 12288);
            #pragma unroll
            for (int i = 0; i < 4; i++) {
                mma_bf16(acc[i][j], aH[i], bH);
                mma_bf16(acc[i][j], aH[i], bL);
                mma_bf16(acc[i][j], aL[i], bH);
            }
        }
    }

    #pragma unroll
    for (int i = 0; i < 4; i++) {
        int gr0 = bm + m0w + i * 16 + trow;
        #pragma unroll
        for (int j = 0; j < 4; j++) {
            int gc = col0 + n0w + j * 8 + tq * 2;
            float2 v0 = make_float2(acc[i][j][0], acc[i][j][1]);
            float2 v1 = make_float2(acc[i][j][2], acc[i][j][3]);
            if (bias) {
                float b0 = bias[gc], b1 = bias[gc + 1];
                v0.x += b0; v0.y += b1;
                v1.x += b0; v1.y += b1;
            }
            if (relu) {
                v0.x = fmaxf(v0.x, 0.f); v0.y = fmaxf(v0.y, 0.f);
                v1.x = fmaxf(v1.x, 0.f); v1.y = fmaxf(v1.y, 0.f);
            }
            *(float2*)&out[(size_t)gr0 * HC + gc]       = v0;
            *(float2*)&out[(size_t)(gr0 + 8) * HC + gc] = v1;
        }
    }
}

// ---------------------------------------------------------------------------
// Fused GATv2 edge phase (pair-unrolled online softmax, R16) WITH fused
// column-stats accumulation: block-level smem sum/sumsq + one global flush.
// No early returns (syncthreads-safe); work guarded by `valid`.
// ---------------------------------------------------------------------------
template <int NV4, int CSH>
__global__ void gat_edge_fused(const float4* __restrict__ xl4,
                               const float4* __restrict__ xr4,
                               const float4* __restrict__ att4,
                               const int* __restrict__ ptr,
                               const int* __restrict__ csrc,
                               float4* __restrict__ out4,
                               float* __restrict__ stats, int Nn) {
    __shared__ float ssum[NV4 * 128];
    __shared__ float ssq [NV4 * 128];
    const int HC  = NV4 * 128;
    const int HC4 = NV4 * 32;

    for (int i = threadIdx.x; i < HC; i += 256) { ssum[i] = 0.f; ssq[i] = 0.f; }
    __syncthreads();

    int gw   = (blockIdx.x * blockDim.x + threadIdx.x) >> 5;
    int lane = threadIdx.x & 31;
    int n    = gw;
    bool valid = (n < Nn);

    float4 o[NV4];
    #pragma unroll
    for (int r = 0; r < NV4; r++) o[r] = make_float4(0.f, 0.f, 0.f, 0.f);

    if (valid) {
        float4 xr[NV4], at[NV4];
        #pragma unroll
        for (int r = 0; r < NV4; r++) {
            xr[r] = xr4[(size_t)n * HC4 + r * 32 + lane];
            at[r] = att4[r * 32 + lane];
        }

        float m[NV4], z[NV4];
        float4 acc[NV4];
        #pragma unroll
        for (int r = 0; r < NV4; r++) {
            m[r] = -1e30f; z[r] = 0.f;
            acc[r] = make_float4(0.f, 0.f, 0.f, 0.f);
        }

        int beg = ptr[n], end = ptr[n + 1];
        int i = beg;
        for (; i + 1 < end; i += 2) {
            int s0 = csrc[i];
            int s1 = csrc[i + 1];
            float4 x0[NV4], x1[NV4];
            #pragma unroll
            for (int r = 0; r < NV4; r++) {
                x0[r] = xl4[(size_t)s0 * HC4 + r * 32 + lane];
                x1[r] = xl4[(size_t)s1 * HC4 + r * 32 + lane];
            }
            float p0[NV4], p1[NV4];
            #pragma unroll
            for (int r = 0; r < NV4; r++) {
                float v, sa = 0.f, sb = 0.f;
                v = x0[r].x + xr[r].x; v = (v > 0.f) ? v : 0.2f * v; sa += at[r].x * v;
                v = x0[r].y + xr[r].y; v = (v > 0.f) ? v : 0.2f * v; sa += at[r].y * v;
                v = x0[r].z + xr[r].z; v = (v > 0.f) ? v : 0.2f * v; sa += at[r].z * v;
                v = x0[r].w + xr[r].w; v = (v > 0.f) ? v : 0.2f * v; sa += at[r].w * v;
                v = x1[r].x + xr[r].x; v = (v > 0.f) ? v : 0.2f * v; sb += at[r].x * v;
                v = x1[r].y + xr[r].y; v = (v > 0.f) ? v : 0.2f * v; sb += at[r].y * v;
                v = x1[r].z + xr[r].z; v = (v > 0.f) ? v : 0.2f * v; sb += at[r].z * v;
                v = x1[r].w + xr[r].w; v = (v > 0.f) ? v : 0.2f * v; sb += at[r].w * v;
                p0[r] = sa; p1[r] = sb;
            }
            #pragma unroll
            for (int r = 0; r < NV4; r++) {
                #pragma unroll
                for (int off = (1 << CSH) >> 1; off > 0; off >>= 1) {
                    p0[r] += __shfl_xor_sync(0xffffffffu, p0[r], off);
                    p1[r] += __shfl_xor_sync(0xffffffffu, p1[r], off);
                }
            }
            #pragma unroll
            for (int r = 0; r < NV4; r++) {
                float mn = fmaxf(m[r], fmaxf(p0[r], p1[r]));
                float sc = expf(m[r] - mn);
                float e0 = expf(p0[r] - mn);
                float e1 = expf(p1[r] - mn);
                z[r] = z[r] * sc + e0 + e1;
                m[r] = mn;
                acc[r].x = acc[r].x * sc + e0 * x0[r].x + e1 * x1[r].x;
                acc[r].y = acc[r].y * sc + e0 * x0[r].y + e1 * x1[r].y;
                acc[r].z = acc[r].z * sc + e0 * x0[r].z + e1 * x1[r].z;
                acc[r].w = acc[r].w * sc + e0 * x0[r].w + e1 * x1[r].w;
            }
        }
        if (i < end) {
            int s0 = csrc[i];
            float4 x0[NV4];
            #pragma unroll
            for (int r = 0; r < NV4; r++)
                x0[r] = xl4[(size_t)s0 * HC4 + r * 32 + lane];
            float p0[NV4];
            #pragma unroll
            for (int r = 0; r < NV4; r++) {
                float v, sa = 0.f;
                v = x0[r].x + xr[r].x; v = (v > 0.f) ? v : 0.2f * v; sa += at[r].x * v;
                v = x0[r].y + xr[r].y; v = (v > 0.f) ? v : 0.2f * v; sa += at[r].y * v;
                v = x0[r].z + xr[r].z; v = (v > 0.f) ? v : 0.2f * v; sa += at[r].z * v;
                v = x0[r].w + xr[r].w; v = (v > 0.f) ? v : 0.2f * v; sa += at[r].w * v;
                p0[r] = sa;
            }
            #pragma unroll
            for (int r = 0; r < NV4; r++) {
                #pragma unroll
                for (int off = (1 << CSH) >> 1; off > 0; off >>= 1)
                    p0[r] += __shfl_xor_sync(0xffffffffu, p0[r], off);
            }
            #pragma unroll
            for (int r = 0; r < NV4; r++) {
                float mn = fmaxf(m[r], p0[r]);
                float sc = expf(m[r] - mn);
                float e0 = expf(p0[r] - mn);
                z[r] = z[r] * sc + e0;
                m[r] = mn;
                acc[r].x = acc[r].x * sc + e0 * x0[r].x;
                acc[r].y = acc[r].y * sc + e0 * x0[r].y;
                acc[r].z = acc[r].z * sc + e0 * x0[r].z;
                acc[r].w = acc[r].w * sc + e0 * x0[r].w;
            }
        }

        #pragma unroll
        for (int r = 0; r < NV4; r++) {
            float inv = 1.f / (z[r] + 1e-16f);
            o[r].x = acc[r].x * inv; o[r].y = acc[r].y * inv;
            o[r].z = acc[r].z * inv; o[r].w = acc[r].w * inv;
            out4[(size_t)n * HC4 + r * 32 + lane] = o[r];
            int cb = (r * 32 + lane) * 4;
            atomicAdd(&ssum[cb + 0], o[r].x); atomicAdd(&ssq[cb + 0], o[r].x * o[r].x);
            atomicAdd(&ssum[cb + 1], o[r].y); atomicAdd(&ssq[cb + 1], o[r].y * o[r].y);
            atomicAdd(&ssum[cb + 2], o[r].z); atomicAdd(&ssq[cb + 2], o[r].z * o[r].z);
            atomicAdd(&ssum[cb + 3], o[r].w); atomicAdd(&ssq[cb + 3], o[r].w * o[r].w);
        }
    }

    __syncthreads();
    for (int i2 = threadIdx.x; i2 < HC; i2 += 256) {
        atomicAdd(&stats[i2],      ssum[i2]);
        atomicAdd(&stats[HC + i2], ssq[i2]);
    }
}

// ---------------------------------------------------------------------------
// GraphNorm
// ---------------------------------------------------------------------------
__global__ void colscale_kernel(const float* __restrict__ stats,
                                const float* __restrict__ bias,
                                const float* __restrict__ gw, const float* __restrict__ gb,
                                const float* __restrict__ gm,
                                float* __restrict__ colA, float* __restrict__ colS,
                                int Nn, int Cn) {
    int c = blockIdx.x * blockDim.x + threadIdx.x;
    if (c >= Cn) return;
    float invN = 1.0f / (float)Nn;
    float ma = stats[c] * invN;
    float q  = stats[Cn + c] * invN;
    float b  = bias[c];
    float mx = ma + b;
    float tt = b - gm[c] * mx;
    float var = q + 2.f * tt * ma + tt * tt;
    var = fmaxf(var, 0.f);
    float A = gw[c] * rsqrtf(var + 1e-5f);
    colA[c] = A;
    colS[c] = A * tt + gb[c];
}

__global__ void norm_relu_split_kernel(float4* __restrict__ x4,
                                       const float4* __restrict__ colA4,
                                       const float4* __restrict__ colS4,
                                       uint32_t* __restrict__ xph,
                                       uint32_t* __restrict__ xpl,
                                       int total4, int Cn4, int wb) {
    int i = blockIdx.x * blockDim.x + threadIdx.x;
    if (i >= total4) return;
    int c = i % Cn4;
    float4 v = x4[i];
    float4 A = colA4[c];
    float4 S = colS4[c];
    v.x = fmaxf(A.x * v.x + S.x, 0.f);
    v.y = fmaxf(A.y * v.y + S.y, 0.f);
    v.z = fmaxf(A.z * v.z + S.z, 0.f);
    v.w = fmaxf(A.w * v.w + S.w, 0.f);
    if (wb) x4[i] = v;
    uint32_t h0, l0, h1, l1;
    packsplit(v.x, v.y, h0, l0);
    packsplit(v.z, v.w, h1, l1);
    xph[2 * i]     = h0; xph[2 * i + 1] = h1;
    xpl[2 * i]     = l0; xpl[2 * i + 1] = l1;
}

// ---------------------------------------------------------------------------
// Pooling
// ---------------------------------------------------------------------------
__global__ void gate_kernel(const float4* __restrict__ hidden4, const float4* __restrict__ aW24,
                            const float* __restrict__ ab2, float* __restrict__ gate, int Nn) {
    int gw   = (blockIdx.x * blockDim.x + threadIdx.x) >> 5;
    int lane = threadIdx.x & 31;
    if (gw >= Nn) return;
    float4 h = hidden4[(size_t)gw * 32 + lane];
    float4 w = aW24[lane];
    float acc = h.x * w.x + h.y * w.y + h.z * w.z + h.w * w.w;
    #pragma unroll
    for (int o = 16; o > 0; o >>= 1) acc += __shfl_down_sync(0xffffffffu, acc, o);
    if (lane == 0) gate[gw] = acc + ab2[0];
}

__device__ __forceinline__ int lower_bound_dev(const int* __restrict__ a, int n, int v) {
    int lo = 0, hi = n;
    while (lo < hi) {
        int mid = (lo + hi) >> 1;
        if (a[mid] < v) lo = mid + 1; else hi = mid;
    }
    return lo;
}

__global__ void pool_kernel(const float* __restrict__ x, const float* __restrict__ gate,
                            const int* __restrict__ batch, float* __restrict__ out, int Nn) {
    __shared__ float red[128];
    __shared__ float wbuf[128];
    int b = blockIdx.x;
    int t = threadIdx.x;
    int beg = lower_bound_dev(batch, Nn, b);
    int end = lower_bound_dev(batch, Nn, b + 1);

    float mx = -1e30f;
    for (int n = beg + t; n < end; n += 128) mx = fmaxf(mx, gate[n]);
    red[t] = mx; __syncthreads();
    for (int o = 64; o > 0; o >>= 1) {
        if (t < o) red[t] = fmaxf(red[t], red[t + o]);
        __syncthreads();
    }
    float m = red[0];
    if (m < -1e29f) m = 0.f;
    __syncthreads();

    float zs = 0.f;
    for (int n = beg + t; n < end; n += 128) zs += expf(gate[n] - m);
    red[t] = zs; __syncthreads();
    for (int o = 64; o > 0; o >>= 1) {
        if (t < o) red[t] += red[t + o];
        __syncthreads();
    }
    float inv = 1.f / (red[0] + 1e-16f);
    __syncthreads();

    float acc = 0.f;
    for (int base = beg; base < end; base += 128) {
        int n = base + t;
        wbuf[t] = (n < end) ? expf(gate[n] - m) * inv : 0.f;
        __syncthreads();
        int cnt = min(128, end - base);
        for (int k = 0; k < cnt; k++)
            acc += wbuf[k] * x[(size_t)(base + k) * 128 + t];
        __syncthreads();
    }
    out[b * 128 + t] = acc;
}

// ---------------------------------------------------------------------------
// Host orchestration
// ---------------------------------------------------------------------------
extern "C" void kernel_launch(void* const* d_in, const int* in_sizes, int n_in,
                              void* d_out, int out_size) {
    const float* x0    = (const float*)d_in[0];
    const int*   ei    = (const int*)d_in[1];
    const int*   batch = (const int*)d_in[2];

    int N = in_sizes[0] / 960;
    int E = in_sizes[1] / 2;
    const int* src = ei;
    const int* dst = ei + E;
    int Et = E + N;

    float *p_xl, *p_xr, *p_a0, *p_a1, *p_stats, *p_colA, *p_colS, *p_hidden, *p_gate;
    uint32_t *p_xph, *p_xpl, *p_wph, *p_wpl;
    int *p_deg, *p_ptr, *p_pos, *p_csrc;
    cudaGetSymbolAddress((void**)&p_xl,    g_xl);
    cudaGetSymbolAddress((void**)&p_xr,    g_xr);
    cudaGetSymbolAddress((void**)&p_a0,    g_act0);
    cudaGetSymbolAddress((void**)&p_a1,    g_act1);
    cudaGetSymbolAddress((void**)&p_stats, g_stats);
    cudaGetSymbolAddress((void**)&p_colA,  g_colA);
    cudaGetSymbolAddress((void**)&p_colS,  g_colS);
    cudaGetSymbolAddress((void**)&p_hidden,g_hidden);
    cudaGetSymbolAddress((void**)&p_gate,  g_gate);
    cudaGetSymbolAddress((void**)&p_xph,   g_xph);
    cudaGetSymbolAddress((void**)&p_xpl,   g_xpl);
    cudaGetSymbolAddress((void**)&p_wph,   g_wph);
    cudaGetSymbolAddress((void**)&p_wpl,   g_wpl);
    cudaGetSymbolAddress((void**)&p_deg,   g_deg);
    cudaGetSymbolAddress((void**)&p_ptr,   g_ptr);
    cudaGetSymbolAddress((void**)&p_pos,   g_pos);
    cudaGetSymbolAddress((void**)&p_csrc,  g_csrc);

    const int woffL[3] = {WOFF_L0L, WOFF_L1L, WOFF_L2L};
    const int woffR[3] = {WOFF_L0R, WOFF_L1R, WOFF_L2R};
    const int din[3] = {960, 512, 256};
    const int Cc[3]  = {128, 64, 32};

    // ---- Launches 1-3: layer-0 operand packs (so launch 4 = GEMM, profiled) ----
    {
        int K2 = 480, HC = 512, nel = K2 * HC;
        split_pack_B_kernel<<<(nel + 255) / 256, 256>>>(
            (const float*)d_in[3], p_wph + WOFF_L0L, p_wpl + WOFF_L0L, K2, HC);
        split_pack_B_kernel<<<(nel + 255) / 256, 256>>>(
            (const float*)d_in[4], p_wph + WOFF_L0R, p_wpl + WOFF_L0R, K2, HC);
    }
    split_pack_A_kernel<<<(N * 480 + 255) / 256, 256>>>(
        (const float2*)x0, p_xph, p_xpl, N * 480);

    // ---- Launch 4: layer-0 dual GEMM (ncu-profiled) ----
    {
        dim3 gblk(2 * 512 / 128, N / 128);
        bf16gemm_pre<<<gblk, 256>>>(p_xph, p_xpl,
                                    p_wph + WOFF_L0L, p_wpl + WOFF_L0L,
                                    p_wph + WOFF_L0R, p_wpl + WOFF_L0R,
                                    p_xl, p_xr, nullptr, 0, N, 480, 512);
    }

    // ---- CSR build ----
    fill_i_kernel<<<(N + 255) / 256, 256>>>(p_deg, 0, N);
    csr_count_kernel<<<(Et + 255) / 256, 256>>>(dst, p_deg, E, N);
    csr_scan_kernel<<<1, 1024>>>(p_deg, p_ptr, p_pos, N);
    csr_scatter_kernel<<<(Et + 255) / 256, 256>>>(src, dst, p_pos, p_csrc, E, N);

    // ---- Remaining weight packs ----
    for (int l = 1; l < 3; l++) {
        int K2 = din[l] / 2, HC = HEADS * Cc[l];
        int nel = K2 * HC;
        split_pack_B_kernel<<<(nel + 255) / 256, 256>>>(
            (const float*)d_in[3 + 7 * l], p_wph + woffL[l], p_wpl + woffL[l], K2, HC);
        split_pack_B_kernel<<<(nel + 255) / 256, 256>>>(
            (const float*)d_in[4 + 7 * l], p_wph + woffR[l], p_wpl + woffR[l], K2, HC);
    }
    split_pack_B_kernel<<<(64 * 128 + 255) / 256, 256>>>(
        (const float*)d_in[24], p_wph + WOFF_AW1, p_wpl + WOFF_AW1, 64, 128);

    float* acts[3] = {p_a0, p_a1, p_a0};

    for (int l = 0; l < 3; l++) {
        int K2 = din[l] / 2;
        int C  = Cc[l];
        int HC = HEADS * C;
        int HC4 = HC / 4;
        const float* att = (const float*)d_in[5 + 7 * l];
        const float* bb  = (const float*)d_in[6 + 7 * l];
        const float* gw  = (const float*)d_in[7 + 7 * l];
        const float* gb  = (const float*)d_in[8 + 7 * l];
        const float* gm  = (const float*)d_in[9 + 7 * l];
        float* out = acts[l];

        if (l > 0) {
            dim3 gblk(2 * HC / 128, N / 128);
            bf16gemm_pre<<<gblk, 256>>>(p_xph, p_xpl,
                                        p_wph + woffL[l], p_wpl + woffL[l],
                                        p_wph + woffR[l], p_wpl + woffR[l],
                                        p_xl, p_xr, nullptr, 0, N, K2, HC);
        }

        // zero stats BEFORE fused edge kernel (stats accumulated in-kernel)
        fill_f_kernel<<<(2 * HC + 255) / 256, 256>>>(p_stats, 0.f, 2 * HC);

        int eblocks = (N * 32 + 255) / 256;
        if (C == 128)
            gat_edge_fused<4, 5><<<eblocks, 256>>>(
                (const float4*)p_xl, (const float4*)p_xr, (const float4*)att,
                p_ptr, p_csrc, (float4*)out, p_stats, N);
        else if (C == 64)
            gat_edge_fused<2, 4><<<eblocks, 256>>>(
                (const float4*)p_xl, (const float4*)p_xr, (const float4*)att,
                p_ptr, p_csrc, (float4*)out, p_stats, N);
        else
            gat_edge_fused<1, 3><<<eblocks, 256>>>(
                (const float4*)p_xl, (const float4*)p_xr, (const float4*)att,
                p_ptr, p_csrc, (float4*)out, p_stats, N);

        colscale_kernel<<<(HC + 255) / 256, 256>>>(p_stats, bb, gw, gb, gm,
                                                   p_colA, p_colS, N, HC);
        norm_relu_split_kernel<<<(N * HC4 + 255) / 256, 256>>>(
            (float4*)out, (const float4*)p_colA, (const float4*)p_colS,
            p_xph, p_xpl, N * HC4, HC4, (l == 2) ? 1 : 0);
    }

    // ---- Pooling ----
    const float* ab1 = (const float*)d_in[25];
    const float* aW2 = (const float*)d_in[26];
    const float* ab2 = (const float*)d_in[27];
    float* xfin = acts[2];

    dim3 hblk(1, N / 128);
    bf16gemm_pre<<<hblk, 256>>>(p_xph, p_xpl,
                                p_wph + WOFF_AW1, p_wpl + WOFF_AW1,
                                nullptr, nullptr,
                                p_hidden, nullptr, ab1, 1, N, 64, 128);
    gate_kernel<<<(N * 32 + 255) / 256, 256>>>((const float4*)p_hidden,
                                               (const float4*)aW2, ab2, p_gate, N);
    pool_kernel<<<NGRAPH, 128>>>(xfin, p_gate, batch, (float*)d_out, N);
}